// round 12
// baseline (speedup 1.0000x reference)
#include <cuda_runtime.h>
#include <cuda_bf16.h>
#include <math.h>

// ---------------- constants ----------------
#define BATCH 32
#define C 80
#define F 2048
#define HW 1024
#define HID 256
#define EDD 64
#define EIN 259            // 4*EDD + 3
#define TEMP_INV 0.4f      // 1/2.5
#define BETA_POS 0.5f
#define GAMMA_NEG 0.25f

// output offsets (flat concat of tuple: W_adj, aw, dlog, cam_vis, refined, total)
#define OUT_WADJ 0
#define OUT_AW   (C*C)                       // 6400
#define OUT_DLOG (OUT_AW + C*F)              // 170240
#define OUT_CAM  (OUT_DLOG + C)              // 170320
#define OUT_REF  (OUT_CAM + BATCH*C*HW)      // 2791760
#define OUT_TOT  (OUT_REF + BATCH*C)         // 2794320

// ---------------- scratch ----------------
struct Scratch {
    float pooledT[F*BATCH];      // [f][b]
    float probs[BATCH*C];
    float yv[BATCH*C];
    float wsum[C];
    float freq[C];
    float Pb[BATCH];
    float present[C];
    float proto[C*F];
    float nrm[C];
    float cosm[C*C];
    float t1[C*HID];
    float Hn[C*HID];
    float Zd[C*EDD];
    float r[C*C];
    float Wadj[C*C];
    float Amat[C*C];
    float Z[C*HID];
    float awun[C*F];
    unsigned awhi[C*F];
    unsigned awlo[C*F];
    float dlog[C];
    float lossbuf[4];
    float cam[(size_t)BATCH*C*HW];
};
__device__ Scratch g_s;

__device__ __forceinline__ float sigm(float x){ return 1.f/(1.f+expf(-x)); }
__device__ __forceinline__ float softplusf(float x){ return fmaxf(x,0.f)+log1pf(expf(-fabsf(x))); }
__device__ __forceinline__ float bcef(float h,float t){ return fmaxf(h,0.f)-h*t+log1pf(expf(-fabsf(h))); }

__device__ __forceinline__ unsigned cvt_tf32(float f){
    unsigned r;
    asm("cvt.rna.tf32.f32 %0, %1;" : "=r"(r) : "f"(f));
    return r;
}

// ---------------- K1: pooled (transposed) + small stats ----------------
__global__ void k_pre(const float* __restrict__ feats, const float* __restrict__ logits,
                      const int* __restrict__ labels){
    if (blockIdx.x < 8192){
        int row = blockIdx.x*8 + (threadIdx.x>>5);
        int lane = threadIdx.x & 31;
        const float4* p = (const float4*)(feats + (size_t)row*HW);
        float s = 0.f;
        #pragma unroll
        for (int i=0;i<8;i++){ float4 v = p[lane + i*32]; s += (v.x+v.y)+(v.z+v.w); }
        #pragma unroll
        for (int o=16;o>0;o>>=1) s += __shfl_down_sync(0xffffffffu,s,o);
        if (lane==0){
            int b = row >> 11, f = row & 2047;
            g_s.pooledT[f*BATCH + b] = s * (1.f/HW);
        }
    } else {
        int t = threadIdx.x;
        for (int i=t;i<BATCH*C;i+=256){
            float p = sigm(logits[i]);
            g_s.probs[i]=p;
            g_s.yv[i]=fmaxf((float)labels[i],0.f);
        }
        __syncthreads();
        if (t<C){
            float s=0.f, pr=0.f;
            for (int b=0;b<BATCH;b++){ s+=g_s.probs[b*C+t]; pr=fmaxf(pr,g_s.yv[b*C+t]); }
            g_s.wsum[t]=fmaxf(s,1e-6f); g_s.freq[t]=s*(1.f/BATCH);
            g_s.present[t]= pr>0.f ? 1.f : 0.f;
        }
        if (t>=128 && t<128+BATCH){
            int b=t-128; float s=0.f;
            for (int c=0;c<C;c++) s+=g_s.probs[b*C+c];
            g_s.Pb[b]=s;
        }
    }
}

// ---------------- K2: proto row + norm, block per class ----------------
__global__ void k_protonorm(){
    int c = blockIdx.x, t = threadIdx.x;
    __shared__ float pc[BATCH];
    __shared__ float red[256];
    if (t < BATCH) pc[t] = g_s.probs[t*C + c];
    __syncthreads();
    float invw = 1.f/g_s.wsum[c];
    float ss = 0.f;
    #pragma unroll
    for (int i=0;i<8;i++){
        int f = i*256 + t;
        const float4* p = (const float4*)(g_s.pooledT + f*BATCH);
        float s = 0.f;
        #pragma unroll
        for (int q=0;q<8;q++){
            float4 v = p[q];
            s += pc[q*4]*v.x + pc[q*4+1]*v.y + pc[q*4+2]*v.z + pc[q*4+3]*v.w;
        }
        float pv = s*invw;
        g_s.proto[(size_t)c*F + f] = pv;
        ss += pv*pv;
    }
    red[t]=ss; __syncthreads();
    for (int o=128;o>0;o>>=1){ if(t<o) red[t]+=red[t+o]; __syncthreads(); }
    if (t==0) g_s.nrm[c] = fmaxf(sqrtf(red[0]),1e-6f);
}

// ---------------- K3: cos, grid (C,4): 20 j per block ----------------
__global__ void k_cos(){
    int i = blockIdx.x;
    __shared__ float si[F];
    for (int k=threadIdx.x;k<F;k+=256) si[k]=g_s.proto[(size_t)i*F+k];
    __syncthreads();
    int w = threadIdx.x>>5, lane = threadIdx.x&31;
    float ni = g_s.nrm[i];
    int jend = blockIdx.y*20 + 20;
    for (int j=blockIdx.y*20+w; j<jend; j+=8){
        const float* pj = g_s.proto + (size_t)j*F;
        float s=0.f;
        #pragma unroll 8
        for (int k=lane;k<F;k+=32) s += si[k]*pj[k];
        #pragma unroll
        for (int o=16;o>0;o>>=1) s += __shfl_down_sync(0xffffffffu,s,o);
        if (lane==0){
            float v = s/(ni*g_s.nrm[j]);
            g_s.cosm[i*C+j] = fminf(fmaxf(v,-1.f),1.f);
        }
    }
}

// ---------------- K4: t1 = relu(proto@pp_w1+b1), grid (10,16), 512 thr ----------------
#define T1_SMEM ((8*2048 + 32*8*16)*4)   // 64KB sx + 16KB red = 80KB
__global__ void k_t1(const float* __restrict__ W, const float* __restrict__ bias){
    extern __shared__ float sm4[];
    float* sx = sm4;            // [8][2048]
    float* red = sm4 + 8*2048;  // [32 kg][8 r][16 jl]
    int m0 = blockIdx.x*8;
    int bj = blockIdx.y;
    int t = threadIdx.x;
    {
        float4* d4 = (float4*)sx;
        const float4* s4 = (const float4*)(g_s.proto + (size_t)m0*F);
        #pragma unroll
        for (int l=t; l<(8*F)/4; l+=512) d4[l] = s4[l];
    }
    __syncthreads();
    int jl = t & 15, kg = t >> 4;   // kg 0..31
    const float* Wp = W + (size_t)(kg*64)*HID + bj*16 + jl;
    float acc[8];
    #pragma unroll
    for (int r=0;r<8;r++) acc[r]=0.f;
    #pragma unroll 16
    for (int k=0;k<64;k++){
        float w = Wp[(size_t)k*HID];
        int ka = kg*64 + k;
        #pragma unroll
        for (int r=0;r<8;r++) acc[r] += sx[r*F+ka]*w;
    }
    #pragma unroll
    for (int r=0;r<8;r++) red[kg*128 + r*16 + jl] = acc[r];
    __syncthreads();
    if (t < 128){
        int r = t>>4, jo = t&15;
        int j = bj*16 + jo;
        float s = 0.f;
        #pragma unroll
        for (int q=0;q<32;q++) s += red[q*128 + r*16 + jo];
        g_s.t1[(size_t)(m0+r)*HID + j] = fmaxf(s + bias[j], 0.f);
    }
}

// ---------------- K5: Hn = t1@pp_w2+b2 ; Zd = relu(Hn@ed_w+ed_b), grid 10, 512 thr ----------------
__global__ void k_hz(const float* __restrict__ W2, const float* __restrict__ b2,
                     const float* __restrict__ EW, const float* __restrict__ EB){
    __shared__ float sx[8*HID];
    __shared__ float sh[8*HID];
    __shared__ float part[8*512];
    int m0 = blockIdx.x*8, t = threadIdx.x;
    {
        float4* d4 = (float4*)sx;
        const float4* s4 = (const float4*)(g_s.t1 + (size_t)m0*HID);
        for (int l=t; l<(8*HID)/4; l+=512) d4[l] = s4[l];
    }
    __syncthreads();
    int j = t & 255, kg = t >> 8;
    float acc[8];
    #pragma unroll
    for (int r=0;r<8;r++) acc[r]=0.f;
    #pragma unroll 8
    for (int k=0;k<128;k++){
        int ka = kg*128 + k;
        float w = W2[(size_t)ka*HID + j];
        #pragma unroll
        for (int r=0;r<8;r++) acc[r] += sx[r*HID+ka]*w;
    }
    if (kg==1){
        #pragma unroll
        for (int r=0;r<8;r++) part[r*256+j] = acc[r];
    }
    __syncthreads();
    if (kg==0){
        float bv = b2[j];
        #pragma unroll
        for (int r=0;r<8;r++){
            float v = acc[r] + part[r*256+j] + bv;
            g_s.Hn[(size_t)(m0+r)*HID + j] = v;
            sh[r*HID+j] = v;
        }
    }
    __syncthreads();
    int j2 = t & 63, kg2 = t >> 6;
    float a2[8];
    #pragma unroll
    for (int r=0;r<8;r++) a2[r]=0.f;
    #pragma unroll 8
    for (int k=0;k<32;k++){
        int ka = kg2*32 + k;
        float w = EW[(size_t)ka*EDD + j2];
        #pragma unroll
        for (int r=0;r<8;r++) a2[r] += sh[r*HID+ka]*w;
    }
    #pragma unroll
    for (int r=0;r<8;r++) part[kg2*512 + r*64 + j2] = a2[r];
    __syncthreads();
    {
        int r3 = t >> 6, j3 = t & 63;
        float s = 0.f;
        #pragma unroll
        for (int q=0;q<8;q++) s += part[q*512 + r3*64 + j3];
        g_s.Zd[(size_t)(m0+r3)*EDD + j3] = fmaxf(s + EB[j3], 0.f);
    }
}

// ---------------- K6: edge MLP, grid (80,2), 5 steps x 8 edges ----------------
__global__ void k_edge(const float* __restrict__ w1, const float* __restrict__ b1,
                       const float* __restrict__ w2, const float* __restrict__ b2,
                       const float* __restrict__ w3, const float* __restrict__ b3){
    extern __shared__ float sm6[];
    float* sw1 = sm6;                // 259*128
    float* sw2 = sw1 + EIN*128;      // 128*64
    float* sw3 = sw2 + 128*64;       // 64
    float* sb1 = sw3 + 64;           // 128
    float* sb2 = sb1 + 128;          // 64
    float* szi = sb2 + 64;           // 64
    float* sfeat = szi + 64;         // 8 edges * 264
    float* sh1 = sfeat + 8*264;      // 8*128
    float* sh2 = sh1 + 8*128;        // 8*64
    int tid = threadIdx.x;
    #pragma unroll 8
    for (int i=tid;i<EIN*128;i+=256) sw1[i]=w1[i];
    #pragma unroll 8
    for (int i=tid;i<128*64;i+=256)  sw2[i]=w2[i];
    if (tid<64)  sw3[tid]=w3[tid];
    if (tid<128) sb1[tid]=b1[tid];
    if (tid<64)  sb2[tid]=b2[tid];
    int iRow = blockIdx.x;
    if (tid<64) szi[tid]=g_s.Zd[iRow*EDD+tid];
    float b3v = b3[0];
    float fi = g_s.freq[iRow];
    __syncthreads();
    int g = tid>>7, lt = tid&127;
    for (int step=0;step<5;step++){
        int jb = blockIdx.y*40 + step*8 + g*4;
        float* fg = sfeat + g*4*264;
        if (lt<64){
            float zi = szi[lt];
            #pragma unroll
            for (int e=0;e<4;e++){
                float zj = g_s.Zd[(jb+e)*EDD + lt];
                float* f = fg + e*264;
                f[lt]      = zi;
                f[64+lt]   = zj;
                f[128+lt]  = fabsf(zi-zj);
                f[192+lt]  = zi*zj;
            }
        } else if (lt==64){
            #pragma unroll
            for (int e=0;e<4;e++){
                float* f = fg + e*264;
                f[256] = g_s.cosm[iRow*C+jb+e];
                f[257] = fi;
                f[258] = g_s.freq[jb+e];
            }
        }
        __syncthreads();
        {
            float a[4] = {0.f,0.f,0.f,0.f};
            #pragma unroll 4
            for (int k=0;k<EIN;k++){
                float w = sw1[k*128+lt];
                #pragma unroll
                for (int e=0;e<4;e++) a[e] += fg[e*264+k]*w;
            }
            float bb = sb1[lt];
            #pragma unroll
            for (int e=0;e<4;e++) sh1[(g*4+e)*128+lt] = fmaxf(a[e]+bb,0.f);
        }
        __syncthreads();
        if (lt<64){
            float a[4] = {0.f,0.f,0.f,0.f};
            #pragma unroll 4
            for (int k=0;k<128;k++){
                float w = sw2[k*64+lt];
                #pragma unroll
                for (int e=0;e<4;e++) a[e] += sh1[(g*4+e)*128+k]*w;
            }
            float bb = sb2[lt];
            #pragma unroll
            for (int e=0;e<4;e++) sh2[(g*4+e)*64+lt] = fmaxf(a[e]+bb,0.f);
        }
        __syncthreads();
        if (lt<32){
            #pragma unroll
            for (int e=0;e<4;e++){
                float v = sh2[(g*4+e)*64+lt]*sw3[lt] + sh2[(g*4+e)*64+32+lt]*sw3[32+lt];
                #pragma unroll
                for (int o=16;o>0;o>>=1) v += __shfl_down_sync(0xffffffffu,v,o);
                if (lt==0) g_s.r[iRow*C+jb+e] = v + b3v;
            }
        }
        __syncthreads();
    }
}
#define EDGE_SMEM ((EIN*128 + 128*64 + 64 + 128 + 64 + 64 + 8*264 + 8*128 + 8*64)*4)

// ---------------- K7: W_adj, A, edge losses, sparsity (1 block) ----------------
__global__ void k_graph(const float* __restrict__ prior, float* __restrict__ out){
    __shared__ float sW[C*C];
    __shared__ float rs[C];
    __shared__ float red[256];
    __shared__ float params[2];
    int t = threadIdx.x;
    for (int idx=t; idx<C*C; idx+=256){
        int i=idx/C, j=idx%C;
        float hij = prior[idx]*TEMP_INV + g_s.r[idx];
        float hji = prior[j*C+i]*TEMP_INV + g_s.r[j*C+i];
        float w = 0.5f*(sigm(hij)+sigm(hji));
        if (i==j) w=0.f;
        sW[idx]=w; g_s.Wadj[idx]=w; out[OUT_WADJ+idx]=w;
    }
    __syncthreads();
    if (t<C){ float s=0.f; for (int j=0;j<C;j++) s+=sW[t*C+j]; rs[t]=fmaxf(s,1e-6f); }
    __syncthreads();
    for (int idx=t; idx<C*C; idx+=256) g_s.Amat[idx]=sW[idx]/rs[idx/C];
    float aP=0.f,aN=0.f,aE=0.f;
    for (int idx=t; idx<C*C; idx+=256){
        int i=idx/C, j=idx%C;
        float em = (i!=j && g_s.present[i]>0.f && g_s.present[j]>0.f)?1.f:0.f;
        float tv = sigm(prior[idx]*TEMP_INV);
        float pf = tv>0.5f?1.f:0.f;
        aP+=pf*em; aN+=(1.f-pf)*em; aE+=em;
    }
    red[t]=aP; __syncthreads();
    for (int o=128;o>0;o>>=1){ if(t<o) red[t]+=red[t+o]; __syncthreads(); }
    float nP = fmaxf(red[0],1.f); __syncthreads();
    red[t]=aN; __syncthreads();
    for (int o=128;o>0;o>>=1){ if(t<o) red[t]+=red[t+o]; __syncthreads(); }
    float nN = fmaxf(red[0],1.f); __syncthreads();
    red[t]=aE; __syncthreads();
    for (int o=128;o>0;o>>=1){ if(t<o) red[t]+=red[t+o]; __syncthreads(); }
    if (t==0){
        params[0] = fminf(fmaxf(nN/nP,1.f),10.f);
        params[1] = fmaxf(red[0],1.f);
    }
    __syncthreads();
    float wpos = params[0], nedges = params[1];
    float aL=0.f,aR=0.f,aS=0.f;
    for (int idx=t; idx<C*C; idx+=256){
        int i=idx/C, j=idx%C;
        float em = (i!=j && g_s.present[i]>0.f && g_s.present[j]>0.f)?1.f:0.f;
        float tv = sigm(prior[idx]*TEMP_INV);
        float h  = prior[idx]*TEMP_INV + g_s.r[idx];
        float wgt = (tv>0.5f)? wpos : 1.f;
        aL += bcef(h,tv)*wgt*em;
        aR += fabsf(g_s.r[idx])*em;
        aS += sW[idx];
    }
    red[t]=aL; __syncthreads();
    for (int o=128;o>0;o>>=1){ if(t<o) red[t]+=red[t+o]; __syncthreads(); }
    float SL = red[0]; __syncthreads();
    red[t]=aR; __syncthreads();
    for (int o=128;o>0;o>>=1){ if(t<o) red[t]+=red[t+o]; __syncthreads(); }
    float SR = red[0]; __syncthreads();
    red[t]=aS; __syncthreads();
    for (int o=128;o>0;o>>=1){ if(t<o) red[t]+=red[t+o]; __syncthreads(); }
    if (t==0){
        g_s.lossbuf[0]=SL/nedges;
        g_s.lossbuf[1]=0.001f*SR/nedges;
        g_s.lossbuf[2]=red[0]/(float)(C*C);
    }
}

// ---------------- K8: GNN step, grid 10, 512 thr ----------------
__global__ void k_gnn(const float* __restrict__ mw1, const float* __restrict__ mb1,
                      const float* __restrict__ mw2, const float* __restrict__ mb2){
    __shared__ float sA[8*C];
    __shared__ float s1[8*HID];
    __shared__ float s2[8*HID];
    __shared__ float part[8*256];
    int m0 = blockIdx.x*8, t = threadIdx.x;
    for (int l=t;l<8*C;l+=512) sA[l]=g_s.Amat[m0*C + l];
    __syncthreads();
    int j = t & 255, kg = t >> 8;
    float acc[8];
    #pragma unroll
    for (int r=0;r<8;r++) acc[r]=0.f;
    #pragma unroll 8
    for (int k=0;k<40;k++){
        int c = kg*40 + k;
        float h = g_s.Hn[(size_t)c*HID + j];
        #pragma unroll
        for (int r=0;r<8;r++) acc[r]+=sA[r*C+c]*h;
    }
    if (kg==1){
        #pragma unroll
        for (int r=0;r<8;r++) part[r*256+j]=acc[r];
    }
    __syncthreads();
    if (kg==0){
        #pragma unroll
        for (int r=0;r<8;r++) s1[r*HID+j] = acc[r] + part[r*256+j];
    }
    __syncthreads();
    float m[8];
    #pragma unroll
    for (int r=0;r<8;r++) m[r]=0.f;
    #pragma unroll 8
    for (int k=0;k<128;k++){
        int ka = kg*128 + k;
        float w = mw1[(size_t)ka*HID+j];
        #pragma unroll
        for (int r=0;r<8;r++) m[r]+=s1[r*HID+ka]*w;
    }
    if (kg==1){
        #pragma unroll
        for (int r=0;r<8;r++) part[r*256+j]=m[r];
    }
    __syncthreads();
    if (kg==0){
        float mb = mb1[j];
        #pragma unroll
        for (int r=0;r<8;r++) s2[r*HID+j] = fmaxf(m[r]+part[r*256+j]+mb, 0.f);
    }
    __syncthreads();
    float z[8];
    #pragma unroll
    for (int r=0;r<8;r++) z[r]=0.f;
    #pragma unroll 8
    for (int k=0;k<128;k++){
        int ka = kg*128 + k;
        float w = mw2[(size_t)ka*HID+j];
        #pragma unroll
        for (int r=0;r<8;r++) z[r]+=s2[r*HID+ka]*w;
    }
    if (kg==1){
        #pragma unroll
        for (int r=0;r<8;r++) part[r*256+j]=z[r];
    }
    __syncthreads();
    if (kg==0){
        float b2 = mb2[j];
        #pragma unroll
        for (int r=0;r<8;r++)
            g_s.Z[(size_t)(m0+r)*HID+j] =
                fmaxf(g_s.Hn[(size_t)(m0+r)*HID+j] + z[r] + part[r*256+j] + b2, 0.f);
    }
}

// ---------------- K9: aw unnormalized, grid (10,8), 512 thr ----------------
__global__ void k_aw1(const float* __restrict__ AW, const float* __restrict__ AB){
    __shared__ float z[8*HID];
    __shared__ float part[8*256];
    int c0 = blockIdx.x*8, bj = blockIdx.y, t = threadIdx.x;
    {
        float4* d4 = (float4*)z;
        const float4* s4 = (const float4*)(g_s.Z + (size_t)c0*HID);
        for (int l=t; l<(8*HID)/4; l+=512) d4[l] = s4[l];
    }
    __syncthreads();
    int j = t & 255, kg = t >> 8;
    int jg = bj*256 + j;
    float acc[8];
    #pragma unroll
    for (int r=0;r<8;r++) acc[r]=0.f;
    #pragma unroll 16
    for (int k=0;k<128;k++){
        int ka = kg*128 + k;
        float w = AW[(size_t)ka*F + jg];
        #pragma unroll
        for (int r=0;r<8;r++) acc[r]+=z[r*HID+ka]*w;
    }
    if (kg==1){
        #pragma unroll
        for (int r=0;r<8;r++) part[r*256+j]=acc[r];
    }
    __syncthreads();
    if (kg==0){
        float b = AB[jg];
        #pragma unroll
        for (int r=0;r<8;r++)
            g_s.awun[(size_t)(c0+r)*F + jg] = softplusf(acc[r]+part[r*256+j]+b);
    }
}

// ---------------- K10: normalize aw, write out + tf32 hi/lo bits, dlog. grid 80 ----------------
__global__ void k_aw2(const float* __restrict__ bias_w, const float* __restrict__ bias_b,
                      float* __restrict__ out){
    __shared__ float red[256];
    int c = blockIdx.x, t = threadIdx.x;
    float vals[8]; float s=0.f;
    #pragma unroll
    for (int i=0;i<8;i++){ vals[i]=g_s.awun[(size_t)c*F + i*256 + t]; s+=vals[i]; }
    red[t]=s; __syncthreads();
    for (int o=128;o>0;o>>=1){ if(t<o) red[t]+=red[t+o]; __syncthreads(); }
    float inv = 1.f/fmaxf(red[0],1e-6f);
    #pragma unroll
    for (int i=0;i<8;i++){
        float v = vals[i]*inv;
        size_t idx = (size_t)c*F + i*256 + t;
        out[OUT_AW + idx] = v;
        unsigned h = cvt_tf32(v);
        g_s.awhi[idx] = h;
        g_s.awlo[idx] = cvt_tf32(v - __uint_as_float(h));
    }
    __syncthreads();
    red[t] = g_s.Z[(size_t)c*HID + t]*bias_w[t]; __syncthreads();
    for (int o=128;o>0;o>>=1){ if(t<o) red[t]+=red[t+o]; __syncthreads(); }
    if (t==0){ float d = red[0]+bias_b[0]; g_s.dlog[c]=d; out[OUT_DLOG+c]=d; }
}

// ---------------- K11: refined + cls_loss + total (1 block) ----------------
__global__ void k_refined(const float* __restrict__ logits, const int* __restrict__ labels,
                          float* __restrict__ out){
    __shared__ float sW[C*C];
    __shared__ float sq[BATCH*C];
    __shared__ float red[256];
    int t = threadIdx.x;
    for (int i=t;i<C*C;i+=256) sW[i]=g_s.Wadj[i];
    for (int i=t;i<BATCH*C;i+=256) sq[i]=g_s.probs[i]*g_s.yv[i];
    __syncthreads();
    float accL=0.f, accM=0.f;
    for (int idx=t; idx<BATCH*C; idx+=256){
        int b=idx/C, d=idx%C;
        float s=0.f;
        #pragma unroll 4
        for (int c=0;c<C;c++) s += sq[b*C+c]*sW[c*C+d];
        float pos = g_s.yv[idx]*s;
        float neg = g_s.Pb[b] - pos;
        float ref = logits[idx] + BETA_POS*pos - GAMMA_NEG*neg + g_s.dlog[d];
        out[OUT_REF+idx] = ref;
        float lab = (float)labels[idx];
        float mflag = (lab != -1.f) ? 1.f : 0.f;
        float safe_t = (mflag>0.f)? lab : 0.f;
        accL += bcef(ref,safe_t)*mflag;
        accM += mflag;
    }
    red[t]=accL; __syncthreads();
    for (int o=128;o>0;o>>=1){ if(t<o) red[t]+=red[t+o]; __syncthreads(); }
    float SL=red[0]; __syncthreads();
    red[t]=accM; __syncthreads();
    for (int o=128;o>0;o>>=1){ if(t<o) red[t]+=red[t+o]; __syncthreads(); }
    if (t==0){
        float cls = SL/fmaxf(red[0],1.f);
        out[OUT_TOT] = cls + 0.1f*g_s.lossbuf[0] + g_s.lossbuf[1] + 0.01f*g_s.lossbuf[2];
    }
}

// ---------------- K12: cam GEMM via tf32 mma.sync ----------------
#define CAM_SMEM 57856
#define BS_STRIDE 136
#define AS_STRIDE 36

__device__ __forceinline__ void mma_tf32(float* c, const unsigned* a, unsigned b0, unsigned b1){
    asm volatile(
        "mma.sync.aligned.m16n8k8.row.col.f32.tf32.tf32.f32 "
        "{%0,%1,%2,%3}, {%4,%5,%6,%7}, {%8,%9}, {%0,%1,%2,%3};\n"
        : "+f"(c[0]), "+f"(c[1]), "+f"(c[2]), "+f"(c[3])
        : "r"(a[0]), "r"(a[1]), "r"(a[2]), "r"(a[3]), "r"(b0), "r"(b1));
}

__global__ void __launch_bounds__(320,2) k_cam(const float* __restrict__ feats){
    extern __shared__ float smem[];
    float* sB = smem;                              // [2][32][136]
    unsigned* sA = (unsigned*)(smem + 2*32*BS_STRIDE); // [2][80][36] (hi, lo)
    int tid = threadIdx.x;
    int lane = tid & 31;
    int w = tid >> 5;
    int g = lane >> 2, tg = lane & 3;
    int wm = w % 5, wn = w / 5;
    int m0 = wm*16;
    int ncol0 = wn*64;
    int nbase = blockIdx.x * 128;
    int b = blockIdx.y;
    const float* Bp = feats + (size_t)b*F*HW + nbase;

    float acc[8][4];
    #pragma unroll
    for (int s=0;s<8;s++)
        #pragma unroll
        for (int i=0;i<4;i++) acc[s][i]=0.f;

    {
        unsigned base = (unsigned)__cvta_generic_to_shared(sB);
        for (int l=tid; l<1024; l+=320){
            int kk = l>>5, c4 = l&31;
            unsigned dst = base + (kk*BS_STRIDE + c4*4)*4;
            const float* src = Bp + (size_t)kk*HW + c4*4;
            asm volatile("cp.async.cg.shared.global [%0], [%1], 16;" :: "r"(dst), "l"(src));
        }
        asm volatile("cp.async.commit_group;");
    }

    for (int kt=0; kt<64; kt++){
        int buf = kt & 1;
        __syncthreads();   // prev MMA done: sA free, sB[buf^1] free for next cp.async
        // A fill: pure copy of precomputed tf32 bits
        {
            int l = tid;
            #pragma unroll
            for (int it=0; it<2; it++, l+=320){
                int m = l>>3, k4 = l&7;
                size_t src = (size_t)m*F + kt*32 + k4*4;
                *(uint4*)(sA + m*AS_STRIDE + k4*4)        = *(const uint4*)(g_s.awhi + src);
                *(uint4*)(sA + 2880 + m*AS_STRIDE + k4*4) = *(const uint4*)(g_s.awlo + src);
            }
        }
        if (kt+1 < 64){
            unsigned base = (unsigned)__cvta_generic_to_shared(sB + (buf^1)*32*BS_STRIDE);
            const float* Bn = Bp + (size_t)(kt+1)*32*HW;
            for (int l=tid; l<1024; l+=320){
                int kk = l>>5, c4 = l&31;
                unsigned dst = base + (kk*BS_STRIDE + c4*4)*4;
                const float* src = Bn + (size_t)kk*HW + c4*4;
                asm volatile("cp.async.cg.shared.global [%0], [%1], 16;" :: "r"(dst), "l"(src));
            }
            asm volatile("cp.async.commit_group;");
            asm volatile("cp.async.wait_group 1;");
        } else {
            asm volatile("cp.async.wait_group 0;");
        }
        // self-cvt: each thread converts exactly the chunks IT cp.async'd (self-visible after wait)
        {
            float* Bb = sB + buf*32*BS_STRIDE;
            for (int l=tid; l<1024; l+=320){
                int kk = l>>5, c4 = l&31;
                float4 v = *(float4*)(Bb + kk*BS_STRIDE + c4*4);
                uint4 u;
                u.x=cvt_tf32(v.x); u.y=cvt_tf32(v.y); u.z=cvt_tf32(v.z); u.w=cvt_tf32(v.w);
                *(uint4*)(Bb + kk*BS_STRIDE + c4*4) = u;
            }
        }
        __syncthreads();   // A fill + B cvt visible to all

        const unsigned* Bt = (const unsigned*)(sB + buf*32*BS_STRIDE);
        #pragma unroll
        for (int k8=0; k8<4; k8++){
            unsigned ahi[4], alo[4];
            int arow0 = (m0+g)*AS_STRIDE + k8*8 + tg;
            int arow1 = (m0+8+g)*AS_STRIDE + k8*8 + tg;
            ahi[0]=sA[arow0];   ahi[1]=sA[arow1];
            ahi[2]=sA[arow0+4]; ahi[3]=sA[arow1+4];
            alo[0]=sA[2880+arow0];   alo[1]=sA[2880+arow1];
            alo[2]=sA[2880+arow0+4]; alo[3]=sA[2880+arow1+4];
            const unsigned* br0 = Bt + (k8*8+tg)*BS_STRIDE + ncol0 + g;
            const unsigned* br1 = br0 + 4*BS_STRIDE;
            #pragma unroll
            for (int s=0;s<8;s++){
                unsigned b0 = br0[s*8];
                unsigned b1 = br1[s*8];
                mma_tf32(acc[s], ahi, b0, b1);
                mma_tf32(acc[s], alo, b0, b1);
            }
        }
    }

    #pragma unroll
    for (int s=0;s<8;s++){
        int cb = nbase + ncol0 + s*8 + tg*2;
        float* d0 = g_s.cam + ((size_t)b*C + m0+g)*HW + cb;
        float* d1 = g_s.cam + ((size_t)b*C + m0+8+g)*HW + cb;
        d0[0]=acc[s][0]; d0[1]=acc[s][1];
        d1[0]=acc[s][2]; d1[1]=acc[s][3];
    }
}

// ---------------- K13: relu + min/max normalize ----------------
__global__ void k_minmax(float* __restrict__ out){
    __shared__ float rmn[256], rmx[256];
    int row = blockIdx.x, t = threadIdx.x;
    const float* base = g_s.cam + (size_t)row*HW;
    float v[4]; float mn=3.4e38f, mx=-3.4e38f;
    #pragma unroll
    for (int i=0;i<4;i++){
        v[i]=fmaxf(base[t+i*256],0.f);
        mn=fminf(mn,v[i]); mx=fmaxf(mx,v[i]);
    }
    rmn[t]=mn; rmx[t]=mx; __syncthreads();
    for (int o=128;o>0;o>>=1){
        if (t<o){ rmn[t]=fminf(rmn[t],rmn[t+o]); rmx[t]=fmaxf(rmx[t],rmx[t+o]); }
        __syncthreads();
    }
    mn=rmn[0]; mx=rmx[0];
    float inv = 1.f/(mx-mn+1e-6f);
    #pragma unroll
    for (int i=0;i<4;i++)
        out[OUT_CAM + (size_t)row*HW + t + i*256] = (v[i]-mn)*inv;
}

// ---------------- launch ----------------
extern "C" void kernel_launch(void* const* d_in, const int* in_sizes, int n_in,
                              void* d_out, int out_size){
    const float* feats   = (const float*)d_in[0];
    const float* logits  = (const float*)d_in[1];
    const int*   labels  = (const int*)d_in[2];
    const float* prior   = (const float*)d_in[3];
    const float* pp_w1   = (const float*)d_in[4];
    const float* pp_b1   = (const float*)d_in[5];
    const float* pp_w2   = (const float*)d_in[6];
    const float* pp_b2   = (const float*)d_in[7];
    const float* msg_w1  = (const float*)d_in[8];
    const float* msg_b1  = (const float*)d_in[9];
    const float* msg_w2  = (const float*)d_in[10];
    const float* msg_b2  = (const float*)d_in[11];
    const float* ed_w    = (const float*)d_in[12];
    const float* ed_b    = (const float*)d_in[13];
    const float* em_w1   = (const float*)d_in[14];
    const float* em_b1   = (const float*)d_in[15];
    const float* em_w2   = (const float*)d_in[16];
    const float* em_b2   = (const float*)d_in[17];
    const float* em_w3   = (const float*)d_in[18];
    const float* em_b3   = (const float*)d_in[19];
    const float* alpha_w = (const float*)d_in[20];
    const float* alpha_b = (const float*)d_in[21];
    const float* bias_w  = (const float*)d_in[22];
    const float* bias_b  = (const float*)d_in[23];
    float* out = (float*)d_out;

    cudaFuncSetAttribute(k_t1,   cudaFuncAttributeMaxDynamicSharedMemorySize, T1_SMEM);
    cudaFuncSetAttribute(k_edge, cudaFuncAttributeMaxDynamicSharedMemorySize, EDGE_SMEM);
    cudaFuncSetAttribute(k_cam,  cudaFuncAttributeMaxDynamicSharedMemorySize, CAM_SMEM);

    k_pre<<<8193,256>>>(feats, logits, labels);
    k_protonorm<<<C,256>>>();
    { dim3 g(C,4); k_cos<<<g,256>>>(); }
    { dim3 g(10,16); k_t1<<<g,512,T1_SMEM>>>(pp_w1, pp_b1); }
    k_hz<<<10,512>>>(pp_w2, pp_b2, ed_w, ed_b);
    { dim3 g(C,2); k_edge<<<g,256,EDGE_SMEM>>>(em_w1, em_b1, em_w2, em_b2, em_w3, em_b3); }
    k_graph<<<1,256>>>(prior, out);
    k_gnn<<<10,512>>>(msg_w1, msg_b1, msg_w2, msg_b2);
    { dim3 g(10,8); k_aw1<<<g,512>>>(alpha_w, alpha_b); }
    k_aw2<<<C,256>>>(bias_w, bias_b, out);
    k_refined<<<1,256>>>(logits, labels, out);
    { dim3 g(HW/128, BATCH); k_cam<<<g,320,CAM_SMEM>>>(feats); }
    k_minmax<<<BATCH*C,256>>>(out);

    (void)in_sizes; (void)n_in; (void)out_size;
}

// round 13
// speedup vs baseline: 1.0253x; 1.0253x over previous
#include <cuda_runtime.h>
#include <cuda_bf16.h>
#include <math.h>

// ---------------- constants ----------------
#define BATCH 32
#define C 80
#define F 2048
#define HW 1024
#define HID 256
#define EDD 64
#define EIN 259            // 4*EDD + 3
#define TEMP_INV 0.4f      // 1/2.5
#define BETA_POS 0.5f
#define GAMMA_NEG 0.25f

// output offsets (flat concat of tuple: W_adj, aw, dlog, cam_vis, refined, total)
#define OUT_WADJ 0
#define OUT_AW   (C*C)                       // 6400
#define OUT_DLOG (OUT_AW + C*F)              // 170240
#define OUT_CAM  (OUT_DLOG + C)              // 170320
#define OUT_REF  (OUT_CAM + BATCH*C*HW)      // 2791760
#define OUT_TOT  (OUT_REF + BATCH*C)         // 2794320

// ---------------- scratch ----------------
struct Scratch {
    float pooledT[F*BATCH];      // [f][b]
    float probs[BATCH*C];
    float yv[BATCH*C];
    float wsum[C];
    float freq[C];
    float Pb[BATCH];
    float present[C];
    float proto[C*F];
    float nrm[C];
    float cosm[C*C];
    float t1[C*HID];
    float Hn[C*HID];
    float Zd[C*EDD];
    float r[C*C];
    float Wadj[C*C];
    float Amat[C*C];
    float Z[C*HID];
    float awun[C*F];
    float dlog[C];
    float lossbuf[4];
    float cam[(size_t)BATCH*C*HW];
};
__device__ Scratch g_s;

__device__ __forceinline__ float sigm(float x){ return 1.f/(1.f+expf(-x)); }
__device__ __forceinline__ float softplusf(float x){ return fmaxf(x,0.f)+log1pf(expf(-fabsf(x))); }
__device__ __forceinline__ float bcef(float h,float t){ return fmaxf(h,0.f)-h*t+log1pf(expf(-fabsf(h))); }

__device__ __forceinline__ unsigned cvt_tf32(float f){
    unsigned r;
    asm("cvt.rna.tf32.f32 %0, %1;" : "=r"(r) : "f"(f));
    return r;
}

// ---------------- K1: pooled (transposed) + small stats ----------------
__global__ void k_pre(const float* __restrict__ feats, const float* __restrict__ logits,
                      const int* __restrict__ labels){
    if (blockIdx.x < 8192){
        int row = blockIdx.x*8 + (threadIdx.x>>5);
        int lane = threadIdx.x & 31;
        const float4* p = (const float4*)(feats + (size_t)row*HW);
        float s = 0.f;
        #pragma unroll
        for (int i=0;i<8;i++){ float4 v = p[lane + i*32]; s += (v.x+v.y)+(v.z+v.w); }
        #pragma unroll
        for (int o=16;o>0;o>>=1) s += __shfl_down_sync(0xffffffffu,s,o);
        if (lane==0){
            int b = row >> 11, f = row & 2047;
            g_s.pooledT[f*BATCH + b] = s * (1.f/HW);
        }
    } else {
        int t = threadIdx.x;
        for (int i=t;i<BATCH*C;i+=256){
            float p = sigm(logits[i]);
            g_s.probs[i]=p;
            g_s.yv[i]=fmaxf((float)labels[i],0.f);
        }
        __syncthreads();
        if (t<C){
            float s=0.f, pr=0.f;
            for (int b=0;b<BATCH;b++){ s+=g_s.probs[b*C+t]; pr=fmaxf(pr,g_s.yv[b*C+t]); }
            g_s.wsum[t]=fmaxf(s,1e-6f); g_s.freq[t]=s*(1.f/BATCH);
            g_s.present[t]= pr>0.f ? 1.f : 0.f;
        }
        if (t>=128 && t<128+BATCH){
            int b=t-128; float s=0.f;
            for (int c=0;c<C;c++) s+=g_s.probs[b*C+c];
            g_s.Pb[b]=s;
        }
    }
}

// ---------------- K2: proto row + norm, block per class ----------------
__global__ void k_protonorm(){
    int c = blockIdx.x, t = threadIdx.x;
    __shared__ float pc[BATCH];
    __shared__ float red[256];
    if (t < BATCH) pc[t] = g_s.probs[t*C + c];
    __syncthreads();
    float invw = 1.f/g_s.wsum[c];
    float ss = 0.f;
    #pragma unroll
    for (int i=0;i<8;i++){
        int f = i*256 + t;
        const float4* p = (const float4*)(g_s.pooledT + f*BATCH);
        float s = 0.f;
        #pragma unroll
        for (int q=0;q<8;q++){
            float4 v = p[q];
            s += pc[q*4]*v.x + pc[q*4+1]*v.y + pc[q*4+2]*v.z + pc[q*4+3]*v.w;
        }
        float pv = s*invw;
        g_s.proto[(size_t)c*F + f] = pv;
        ss += pv*pv;
    }
    red[t]=ss; __syncthreads();
    for (int o=128;o>0;o>>=1){ if(t<o) red[t]+=red[t+o]; __syncthreads(); }
    if (t==0) g_s.nrm[c] = fmaxf(sqrtf(red[0]),1e-6f);
}

// ---------------- K3: cos, grid (C,4): 20 j per block ----------------
__global__ void k_cos(){
    int i = blockIdx.x;
    __shared__ float si[F];
    for (int k=threadIdx.x;k<F;k+=256) si[k]=g_s.proto[(size_t)i*F+k];
    __syncthreads();
    int w = threadIdx.x>>5, lane = threadIdx.x&31;
    float ni = g_s.nrm[i];
    int jend = blockIdx.y*20 + 20;
    for (int j=blockIdx.y*20+w; j<jend; j+=8){
        const float* pj = g_s.proto + (size_t)j*F;
        float s=0.f;
        #pragma unroll 8
        for (int k=lane;k<F;k+=32) s += si[k]*pj[k];
        #pragma unroll
        for (int o=16;o>0;o>>=1) s += __shfl_down_sync(0xffffffffu,s,o);
        if (lane==0){
            float v = s/(ni*g_s.nrm[j]);
            g_s.cosm[i*C+j] = fminf(fmaxf(v,-1.f),1.f);
        }
    }
}

// ---------------- K4: t1 = relu(proto@pp_w1+b1), grid (10,16), 512 thr ----------------
#define T1_SMEM ((8*2048 + 32*8*16)*4)   // 64KB sx + 16KB red = 80KB
__global__ void k_t1(const float* __restrict__ W, const float* __restrict__ bias){
    extern __shared__ float sm4[];
    float* sx = sm4;            // [8][2048]
    float* red = sm4 + 8*2048;  // [32 kg][8 r][16 jl]
    int m0 = blockIdx.x*8;
    int bj = blockIdx.y;
    int t = threadIdx.x;
    {
        float4* d4 = (float4*)sx;
        const float4* s4 = (const float4*)(g_s.proto + (size_t)m0*F);
        #pragma unroll
        for (int l=t; l<(8*F)/4; l+=512) d4[l] = s4[l];
    }
    __syncthreads();
    int jl = t & 15, kg = t >> 4;   // kg 0..31
    const float* Wp = W + (size_t)(kg*64)*HID + bj*16 + jl;
    float acc[8];
    #pragma unroll
    for (int r=0;r<8;r++) acc[r]=0.f;
    #pragma unroll 16
    for (int k=0;k<64;k++){
        float w = Wp[(size_t)k*HID];
        int ka = kg*64 + k;
        #pragma unroll
        for (int r=0;r<8;r++) acc[r] += sx[r*F+ka]*w;
    }
    #pragma unroll
    for (int r=0;r<8;r++) red[kg*128 + r*16 + jl] = acc[r];
    __syncthreads();
    if (t < 128){
        int r = t>>4, jo = t&15;
        int j = bj*16 + jo;
        float s = 0.f;
        #pragma unroll
        for (int q=0;q<32;q++) s += red[q*128 + r*16 + jo];
        g_s.t1[(size_t)(m0+r)*HID + j] = fmaxf(s + bias[j], 0.f);
    }
}

// ---------------- K5: Hn = t1@pp_w2+b2 ; Zd = relu(Hn@ed_w+ed_b), grid 10, 512 thr ----------------
__global__ void k_hz(const float* __restrict__ W2, const float* __restrict__ b2,
                     const float* __restrict__ EW, const float* __restrict__ EB){
    __shared__ float sx[8*HID];
    __shared__ float sh[8*HID];
    __shared__ float part[8*512];
    int m0 = blockIdx.x*8, t = threadIdx.x;
    {
        float4* d4 = (float4*)sx;
        const float4* s4 = (const float4*)(g_s.t1 + (size_t)m0*HID);
        for (int l=t; l<(8*HID)/4; l+=512) d4[l] = s4[l];
    }
    __syncthreads();
    int j = t & 255, kg = t >> 8;
    float acc[8];
    #pragma unroll
    for (int r=0;r<8;r++) acc[r]=0.f;
    #pragma unroll 8
    for (int k=0;k<128;k++){
        int ka = kg*128 + k;
        float w = W2[(size_t)ka*HID + j];
        #pragma unroll
        for (int r=0;r<8;r++) acc[r] += sx[r*HID+ka]*w;
    }
    if (kg==1){
        #pragma unroll
        for (int r=0;r<8;r++) part[r*256+j] = acc[r];
    }
    __syncthreads();
    if (kg==0){
        float bv = b2[j];
        #pragma unroll
        for (int r=0;r<8;r++){
            float v = acc[r] + part[r*256+j] + bv;
            g_s.Hn[(size_t)(m0+r)*HID + j] = v;
            sh[r*HID+j] = v;
        }
    }
    __syncthreads();
    int j2 = t & 63, kg2 = t >> 6;
    float a2[8];
    #pragma unroll
    for (int r=0;r<8;r++) a2[r]=0.f;
    #pragma unroll 8
    for (int k=0;k<32;k++){
        int ka = kg2*32 + k;
        float w = EW[(size_t)ka*EDD + j2];
        #pragma unroll
        for (int r=0;r<8;r++) a2[r] += sh[r*HID+ka]*w;
    }
    #pragma unroll
    for (int r=0;r<8;r++) part[kg2*512 + r*64 + j2] = a2[r];
    __syncthreads();
    {
        int r3 = t >> 6, j3 = t & 63;
        float s = 0.f;
        #pragma unroll
        for (int q=0;q<8;q++) s += part[q*512 + r3*64 + j3];
        g_s.Zd[(size_t)(m0+r3)*EDD + j3] = fmaxf(s + EB[j3], 0.f);
    }
}

// ---------------- K6: edge MLP, grid (80,2), 5 steps x 8 edges ----------------
__global__ void k_edge(const float* __restrict__ w1, const float* __restrict__ b1,
                       const float* __restrict__ w2, const float* __restrict__ b2,
                       const float* __restrict__ w3, const float* __restrict__ b3){
    extern __shared__ float sm6[];
    float* sw1 = sm6;                // 259*128
    float* sw2 = sw1 + EIN*128;      // 128*64
    float* sw3 = sw2 + 128*64;       // 64
    float* sb1 = sw3 + 64;           // 128
    float* sb2 = sb1 + 128;          // 64
    float* szi = sb2 + 64;           // 64
    float* sfeat = szi + 64;         // 8 edges * 264
    float* sh1 = sfeat + 8*264;      // 8*128
    float* sh2 = sh1 + 8*128;        // 8*64
    int tid = threadIdx.x;
    #pragma unroll 8
    for (int i=tid;i<EIN*128;i+=256) sw1[i]=w1[i];
    #pragma unroll 8
    for (int i=tid;i<128*64;i+=256)  sw2[i]=w2[i];
    if (tid<64)  sw3[tid]=w3[tid];
    if (tid<128) sb1[tid]=b1[tid];
    if (tid<64)  sb2[tid]=b2[tid];
    int iRow = blockIdx.x;
    if (tid<64) szi[tid]=g_s.Zd[iRow*EDD+tid];
    float b3v = b3[0];
    float fi = g_s.freq[iRow];
    __syncthreads();
    int g = tid>>7, lt = tid&127;
    for (int step=0;step<5;step++){
        int jb = blockIdx.y*40 + step*8 + g*4;
        float* fg = sfeat + g*4*264;
        if (lt<64){
            float zi = szi[lt];
            #pragma unroll
            for (int e=0;e<4;e++){
                float zj = g_s.Zd[(jb+e)*EDD + lt];
                float* f = fg + e*264;
                f[lt]      = zi;
                f[64+lt]   = zj;
                f[128+lt]  = fabsf(zi-zj);
                f[192+lt]  = zi*zj;
            }
        } else if (lt==64){
            #pragma unroll
            for (int e=0;e<4;e++){
                float* f = fg + e*264;
                f[256] = g_s.cosm[iRow*C+jb+e];
                f[257] = fi;
                f[258] = g_s.freq[jb+e];
            }
        }
        __syncthreads();
        {
            float a[4] = {0.f,0.f,0.f,0.f};
            #pragma unroll 4
            for (int k=0;k<EIN;k++){
                float w = sw1[k*128+lt];
                #pragma unroll
                for (int e=0;e<4;e++) a[e] += fg[e*264+k]*w;
            }
            float bb = sb1[lt];
            #pragma unroll
            for (int e=0;e<4;e++) sh1[(g*4+e)*128+lt] = fmaxf(a[e]+bb,0.f);
        }
        __syncthreads();
        if (lt<64){
            float a[4] = {0.f,0.f,0.f,0.f};
            #pragma unroll 4
            for (int k=0;k<128;k++){
                float w = sw2[k*64+lt];
                #pragma unroll
                for (int e=0;e<4;e++) a[e] += sh1[(g*4+e)*128+k]*w;
            }
            float bb = sb2[lt];
            #pragma unroll
            for (int e=0;e<4;e++) sh2[(g*4+e)*64+lt] = fmaxf(a[e]+bb,0.f);
        }
        __syncthreads();
        if (lt<32){
            #pragma unroll
            for (int e=0;e<4;e++){
                float v = sh2[(g*4+e)*64+lt]*sw3[lt] + sh2[(g*4+e)*64+32+lt]*sw3[32+lt];
                #pragma unroll
                for (int o=16;o>0;o>>=1) v += __shfl_down_sync(0xffffffffu,v,o);
                if (lt==0) g_s.r[iRow*C+jb+e] = v + b3v;
            }
        }
        __syncthreads();
    }
}
#define EDGE_SMEM ((EIN*128 + 128*64 + 64 + 128 + 64 + 64 + 8*264 + 8*128 + 8*64)*4)

// ---------------- K7: W_adj, A, edge losses, sparsity (1 block) ----------------
__global__ void k_graph(const float* __restrict__ prior, float* __restrict__ out){
    __shared__ float sW[C*C];
    __shared__ float rs[C];
    __shared__ float red[256];
    __shared__ float params[2];
    int t = threadIdx.x;
    for (int idx=t; idx<C*C; idx+=256){
        int i=idx/C, j=idx%C;
        float hij = prior[idx]*TEMP_INV + g_s.r[idx];
        float hji = prior[j*C+i]*TEMP_INV + g_s.r[j*C+i];
        float w = 0.5f*(sigm(hij)+sigm(hji));
        if (i==j) w=0.f;
        sW[idx]=w; g_s.Wadj[idx]=w; out[OUT_WADJ+idx]=w;
    }
    __syncthreads();
    if (t<C){ float s=0.f; for (int j=0;j<C;j++) s+=sW[t*C+j]; rs[t]=fmaxf(s,1e-6f); }
    __syncthreads();
    for (int idx=t; idx<C*C; idx+=256) g_s.Amat[idx]=sW[idx]/rs[idx/C];
    float aP=0.f,aN=0.f,aE=0.f;
    for (int idx=t; idx<C*C; idx+=256){
        int i=idx/C, j=idx%C;
        float em = (i!=j && g_s.present[i]>0.f && g_s.present[j]>0.f)?1.f:0.f;
        float tv = sigm(prior[idx]*TEMP_INV);
        float pf = tv>0.5f?1.f:0.f;
        aP+=pf*em; aN+=(1.f-pf)*em; aE+=em;
    }
    red[t]=aP; __syncthreads();
    for (int o=128;o>0;o>>=1){ if(t<o) red[t]+=red[t+o]; __syncthreads(); }
    float nP = fmaxf(red[0],1.f); __syncthreads();
    red[t]=aN; __syncthreads();
    for (int o=128;o>0;o>>=1){ if(t<o) red[t]+=red[t+o]; __syncthreads(); }
    float nN = fmaxf(red[0],1.f); __syncthreads();
    red[t]=aE; __syncthreads();
    for (int o=128;o>0;o>>=1){ if(t<o) red[t]+=red[t+o]; __syncthreads(); }
    if (t==0){
        params[0] = fminf(fmaxf(nN/nP,1.f),10.f);
        params[1] = fmaxf(red[0],1.f);
    }
    __syncthreads();
    float wpos = params[0], nedges = params[1];
    float aL=0.f,aR=0.f,aS=0.f;
    for (int idx=t; idx<C*C; idx+=256){
        int i=idx/C, j=idx%C;
        float em = (i!=j && g_s.present[i]>0.f && g_s.present[j]>0.f)?1.f:0.f;
        float tv = sigm(prior[idx]*TEMP_INV);
        float h  = prior[idx]*TEMP_INV + g_s.r[idx];
        float wgt = (tv>0.5f)? wpos : 1.f;
        aL += bcef(h,tv)*wgt*em;
        aR += fabsf(g_s.r[idx])*em;
        aS += sW[idx];
    }
    red[t]=aL; __syncthreads();
    for (int o=128;o>0;o>>=1){ if(t<o) red[t]+=red[t+o]; __syncthreads(); }
    float SL = red[0]; __syncthreads();
    red[t]=aR; __syncthreads();
    for (int o=128;o>0;o>>=1){ if(t<o) red[t]+=red[t+o]; __syncthreads(); }
    float SR = red[0]; __syncthreads();
    red[t]=aS; __syncthreads();
    for (int o=128;o>0;o>>=1){ if(t<o) red[t]+=red[t+o]; __syncthreads(); }
    if (t==0){
        g_s.lossbuf[0]=SL/nedges;
        g_s.lossbuf[1]=0.001f*SR/nedges;
        g_s.lossbuf[2]=red[0]/(float)(C*C);
    }
}

// ---------------- K8: GNN step, grid 10, 512 thr ----------------
__global__ void k_gnn(const float* __restrict__ mw1, const float* __restrict__ mb1,
                      const float* __restrict__ mw2, const float* __restrict__ mb2){
    __shared__ float sA[8*C];
    __shared__ float s1[8*HID];
    __shared__ float s2[8*HID];
    __shared__ float part[8*256];
    int m0 = blockIdx.x*8, t = threadIdx.x;
    for (int l=t;l<8*C;l+=512) sA[l]=g_s.Amat[m0*C + l];
    __syncthreads();
    int j = t & 255, kg = t >> 8;
    float acc[8];
    #pragma unroll
    for (int r=0;r<8;r++) acc[r]=0.f;
    #pragma unroll 8
    for (int k=0;k<40;k++){
        int c = kg*40 + k;
        float h = g_s.Hn[(size_t)c*HID + j];
        #pragma unroll
        for (int r=0;r<8;r++) acc[r]+=sA[r*C+c]*h;
    }
    if (kg==1){
        #pragma unroll
        for (int r=0;r<8;r++) part[r*256+j]=acc[r];
    }
    __syncthreads();
    if (kg==0){
        #pragma unroll
        for (int r=0;r<8;r++) s1[r*HID+j] = acc[r] + part[r*256+j];
    }
    __syncthreads();
    float m[8];
    #pragma unroll
    for (int r=0;r<8;r++) m[r]=0.f;
    #pragma unroll 8
    for (int k=0;k<128;k++){
        int ka = kg*128 + k;
        float w = mw1[(size_t)ka*HID+j];
        #pragma unroll
        for (int r=0;r<8;r++) m[r]+=s1[r*HID+ka]*w;
    }
    if (kg==1){
        #pragma unroll
        for (int r=0;r<8;r++) part[r*256+j]=m[r];
    }
    __syncthreads();
    if (kg==0){
        float mb = mb1[j];
        #pragma unroll
        for (int r=0;r<8;r++) s2[r*HID+j] = fmaxf(m[r]+part[r*256+j]+mb, 0.f);
    }
    __syncthreads();
    float z[8];
    #pragma unroll
    for (int r=0;r<8;r++) z[r]=0.f;
    #pragma unroll 8
    for (int k=0;k<128;k++){
        int ka = kg*128 + k;
        float w = mw2[(size_t)ka*HID+j];
        #pragma unroll
        for (int r=0;r<8;r++) z[r]+=s2[r*HID+ka]*w;
    }
    if (kg==1){
        #pragma unroll
        for (int r=0;r<8;r++) part[r*256+j]=z[r];
    }
    __syncthreads();
    if (kg==0){
        float b2 = mb2[j];
        #pragma unroll
        for (int r=0;r<8;r++)
            g_s.Z[(size_t)(m0+r)*HID+j] =
                fmaxf(g_s.Hn[(size_t)(m0+r)*HID+j] + z[r] + part[r*256+j] + b2, 0.f);
    }
}

// ---------------- K9: aw unnormalized, grid (10,8), 512 thr ----------------
__global__ void k_aw1(const float* __restrict__ AW, const float* __restrict__ AB){
    __shared__ float z[8*HID];
    __shared__ float part[8*256];
    int c0 = blockIdx.x*8, bj = blockIdx.y, t = threadIdx.x;
    {
        float4* d4 = (float4*)z;
        const float4* s4 = (const float4*)(g_s.Z + (size_t)c0*HID);
        for (int l=t; l<(8*HID)/4; l+=512) d4[l] = s4[l];
    }
    __syncthreads();
    int j = t & 255, kg = t >> 8;
    int jg = bj*256 + j;
    float acc[8];
    #pragma unroll
    for (int r=0;r<8;r++) acc[r]=0.f;
    #pragma unroll 16
    for (int k=0;k<128;k++){
        int ka = kg*128 + k;
        float w = AW[(size_t)ka*F + jg];
        #pragma unroll
        for (int r=0;r<8;r++) acc[r]+=z[r*HID+ka]*w;
    }
    if (kg==1){
        #pragma unroll
        for (int r=0;r<8;r++) part[r*256+j]=acc[r];
    }
    __syncthreads();
    if (kg==0){
        float b = AB[jg];
        #pragma unroll
        for (int r=0;r<8;r++)
            g_s.awun[(size_t)(c0+r)*F + jg] = softplusf(acc[r]+part[r*256+j]+b);
    }
}

// ---------------- K10: normalize aw, write out, compute dlog. grid 80 ----------------
__global__ void k_aw2(const float* __restrict__ bias_w, const float* __restrict__ bias_b,
                      float* __restrict__ out){
    __shared__ float red[256];
    int c = blockIdx.x, t = threadIdx.x;
    float vals[8]; float s=0.f;
    #pragma unroll
    for (int i=0;i<8;i++){ vals[i]=g_s.awun[(size_t)c*F + i*256 + t]; s+=vals[i]; }
    red[t]=s; __syncthreads();
    for (int o=128;o>0;o>>=1){ if(t<o) red[t]+=red[t+o]; __syncthreads(); }
    float inv = 1.f/fmaxf(red[0],1e-6f);
    #pragma unroll
    for (int i=0;i<8;i++) out[OUT_AW + (size_t)c*F + i*256 + t] = vals[i]*inv;
    __syncthreads();
    red[t] = g_s.Z[(size_t)c*HID + t]*bias_w[t]; __syncthreads();
    for (int o=128;o>0;o>>=1){ if(t<o) red[t]+=red[t+o]; __syncthreads(); }
    if (t==0){ float d = red[0]+bias_b[0]; g_s.dlog[c]=d; out[OUT_DLOG+c]=d; }
}

// ---------------- K11: refined + cls_loss + total (1 block) ----------------
__global__ void k_refined(const float* __restrict__ logits, const int* __restrict__ labels,
                          float* __restrict__ out){
    __shared__ float sW[C*C];
    __shared__ float sq[BATCH*C];
    __shared__ float red[256];
    int t = threadIdx.x;
    for (int i=t;i<C*C;i+=256) sW[i]=g_s.Wadj[i];
    for (int i=t;i<BATCH*C;i+=256) sq[i]=g_s.probs[i]*g_s.yv[i];
    __syncthreads();
    float accL=0.f, accM=0.f;
    for (int idx=t; idx<BATCH*C; idx+=256){
        int b=idx/C, d=idx%C;
        float s=0.f;
        #pragma unroll 4
        for (int c=0;c<C;c++) s += sq[b*C+c]*sW[c*C+d];
        float pos = g_s.yv[idx]*s;
        float neg = g_s.Pb[b] - pos;
        float ref = logits[idx] + BETA_POS*pos - GAMMA_NEG*neg + g_s.dlog[d];
        out[OUT_REF+idx] = ref;
        float lab = (float)labels[idx];
        float mflag = (lab != -1.f) ? 1.f : 0.f;
        float safe_t = (mflag>0.f)? lab : 0.f;
        accL += bcef(ref,safe_t)*mflag;
        accM += mflag;
    }
    red[t]=accL; __syncthreads();
    for (int o=128;o>0;o>>=1){ if(t<o) red[t]+=red[t+o]; __syncthreads(); }
    float SL=red[0]; __syncthreads();
    red[t]=accM; __syncthreads();
    for (int o=128;o>0;o>>=1){ if(t<o) red[t]+=red[t+o]; __syncthreads(); }
    if (t==0){
        float cls = SL/fmaxf(red[0],1.f);
        out[OUT_TOT] = cls + 0.1f*g_s.lossbuf[0] + g_s.lossbuf[1] + 0.01f*g_s.lossbuf[2];
    }
}

// ---------------- K12: cam GEMM via tf32 mma.sync, 3-stage cp.async pipeline ----------------
#define BS_STRIDE 136
#define AS_STRIDE 36
#define CAM_SMEM ((3*32*BS_STRIDE + 2*80*AS_STRIDE)*4)   // 52224 + 23040 = 75264 B

__device__ __forceinline__ void mma_tf32(float* c, const unsigned* a, unsigned b0, unsigned b1){
    asm volatile(
        "mma.sync.aligned.m16n8k8.row.col.f32.tf32.tf32.f32 "
        "{%0,%1,%2,%3}, {%4,%5,%6,%7}, {%8,%9}, {%0,%1,%2,%3};\n"
        : "+f"(c[0]), "+f"(c[1]), "+f"(c[2]), "+f"(c[3])
        : "r"(a[0]), "r"(a[1]), "r"(a[2]), "r"(a[3]), "r"(b0), "r"(b1));
}

__global__ void __launch_bounds__(320,2) k_cam(const float* __restrict__ feats,
                                               const float* __restrict__ aw){
    extern __shared__ float smem[];
    float* sB = smem;                                  // [3][32][136]
    unsigned* sA = (unsigned*)(smem + 3*32*BS_STRIDE); // [2][80][36] (hi, lo)
    int tid = threadIdx.x;
    int lane = tid & 31;
    int w = tid >> 5;
    int g = lane >> 2, tg = lane & 3;
    int wm = w % 5, wn = w / 5;
    int m0 = wm*16;
    int ncol0 = wn*64;
    int nbase = blockIdx.x * 128;
    int b = blockIdx.y;
    const float* Bp = feats + (size_t)b*F*HW + nbase;

    float acc[8][4];
    #pragma unroll
    for (int s=0;s<8;s++)
        #pragma unroll
        for (int i=0;i<4;i++) acc[s][i]=0.f;

    // prologue: issue tiles 0 and 1
    #pragma unroll
    for (int pk=0; pk<2; pk++){
        unsigned base = (unsigned)__cvta_generic_to_shared(sB + (pk%3)*32*BS_STRIDE);
        const float* Bn = Bp + (size_t)pk*32*HW;
        for (int l=tid; l<1024; l+=320){
            int kk = l>>5, c4 = l&31;
            unsigned dst = base + (kk*BS_STRIDE + c4*4)*4;
            const float* src = Bn + (size_t)kk*HW + c4*4;
            asm volatile("cp.async.cg.shared.global [%0], [%1], 16;" :: "r"(dst), "l"(src));
        }
        asm volatile("cp.async.commit_group;");
    }

    for (int kt=0; kt<64; kt++){
        int buf = kt % 3;
        __syncthreads();   // prev MMA done: sA free, sB[(kt+2)%3] free
        // A fill: on-the-fly tf32 hi/lo split (aw L2-resident)
        {
            int l = tid;
            #pragma unroll
            for (int it=0; it<2; it++, l+=320){
                int m = l>>3, k4 = l&7;
                float4 v = *(const float4*)(aw + (size_t)m*F + kt*32 + k4*4);
                unsigned* hi = sA + m*AS_STRIDE + k4*4;
                unsigned* lo = hi + 80*AS_STRIDE;
                unsigned h0=cvt_tf32(v.x), h1=cvt_tf32(v.y), h2=cvt_tf32(v.z), h3=cvt_tf32(v.w);
                hi[0]=h0; hi[1]=h1; hi[2]=h2; hi[3]=h3;
                lo[0]=cvt_tf32(v.x-__uint_as_float(h0));
                lo[1]=cvt_tf32(v.y-__uint_as_float(h1));
                lo[2]=cvt_tf32(v.z-__uint_as_float(h2));
                lo[3]=cvt_tf32(v.w-__uint_as_float(h3));
            }
        }
        // issue tile kt+2; wait for tile kt's group
        if (kt+2 < 64){
            unsigned base = (unsigned)__cvta_generic_to_shared(sB + ((kt+2)%3)*32*BS_STRIDE);
            const float* Bn = Bp + (size_t)(kt+2)*32*HW;
            for (int l=tid; l<1024; l+=320){
                int kk = l>>5, c4 = l&31;
                unsigned dst = base + (kk*BS_STRIDE + c4*4)*4;
                const float* src = Bn + (size_t)kk*HW + c4*4;
                asm volatile("cp.async.cg.shared.global [%0], [%1], 16;" :: "r"(dst), "l"(src));
            }
            asm volatile("cp.async.commit_group;");
            asm volatile("cp.async.wait_group 2;");
        } else if (kt+1 < 64){
            asm volatile("cp.async.wait_group 1;");
        } else {
            asm volatile("cp.async.wait_group 0;");
        }
        // self-cvt: each thread converts exactly the chunks IT cp.async'd
        {
            float* Bb = sB + buf*32*BS_STRIDE;
            for (int l=tid; l<1024; l+=320){
                int kk = l>>5, c4 = l&31;
                float4 v = *(float4*)(Bb + kk*BS_STRIDE + c4*4);
                uint4 u;
                u.x=cvt_tf32(v.x); u.y=cvt_tf32(v.y); u.z=cvt_tf32(v.z); u.w=cvt_tf32(v.w);
                *(uint4*)(Bb + kk*BS_STRIDE + c4*4) = u;
            }
        }
        __syncthreads();   // A fill + B cvt visible to all

        const unsigned* Bt = (const unsigned*)(sB + buf*32*BS_STRIDE);
        #pragma unroll
        for (int k8=0; k8<4; k8++){
            unsigned ahi[4], alo[4];
            int arow0 = (m0+g)*AS_STRIDE + k8*8 + tg;
            int arow1 = (m0+8+g)*AS_STRIDE + k8*8 + tg;
            ahi[0]=sA[arow0];   ahi[1]=sA[arow1];
            ahi[2]=sA[arow0+4]; ahi[3]=sA[arow1+4];
            alo[0]=sA[2880+arow0];   alo[1]=sA[2880+arow1];
            alo[2]=sA[2880+arow0+4]; alo[3]=sA[2880+arow1+4];
            const unsigned* br0 = Bt + (k8*8+tg)*BS_STRIDE + ncol0 + g;
            const unsigned* br1 = br0 + 4*BS_STRIDE;
            #pragma unroll
            for (int s=0;s<8;s++){
                unsigned b0 = br0[s*8];
                unsigned b1 = br1[s*8];
                mma_tf32(acc[s], ahi, b0, b1);
                mma_tf32(acc[s], alo, b0, b1);
            }
        }
    }

    #pragma unroll
    for (int s=0;s<8;s++){
        int cb = nbase + ncol0 + s*8 + tg*2;
        float* d0 = g_s.cam + ((size_t)b*C + m0+g)*HW + cb;
        float* d1 = g_s.cam + ((size_t)b*C + m0+8+g)*HW + cb;
        d0[0]=acc[s][0]; d0[1]=acc[s][1];
        d1[0]=acc[s][2]; d1[1]=acc[s][3];
    }
}

// ---------------- K13: relu + min/max normalize ----------------
__global__ void k_minmax(float* __restrict__ out){
    __shared__ float rmn[256], rmx[256];
    int row = blockIdx.x, t = threadIdx.x;
    const float* base = g_s.cam + (size_t)row*HW;
    float v[4]; float mn=3.4e38f, mx=-3.4e38f;
    #pragma unroll
    for (int i=0;i<4;i++){
        v[i]=fmaxf(base[t+i*256],0.f);
        mn=fminf(mn,v[i]); mx=fmaxf(mx,v[i]);
    }
    rmn[t]=mn; rmx[t]=mx; __syncthreads();
    for (int o=128;o>0;o>>=1){
        if (t<o){ rmn[t]=fminf(rmn[t],rmn[t+o]); rmx[t]=fmaxf(rmx[t],rmx[t+o]); }
        __syncthreads();
    }
    mn=rmn[0]; mx=rmx[0];
    float inv = 1.f/(mx-mn+1e-6f);
    #pragma unroll
    for (int i=0;i<4;i++)
        out[OUT_CAM + (size_t)row*HW + t + i*256] = (v[i]-mn)*inv;
}

// ---------------- launch ----------------
extern "C" void kernel_launch(void* const* d_in, const int* in_sizes, int n_in,
                              void* d_out, int out_size){
    const float* feats   = (const float*)d_in[0];
    const float* logits  = (const float*)d_in[1];
    const int*   labels  = (const int*)d_in[2];
    const float* prior   = (const float*)d_in[3];
    const float* pp_w1   = (const float*)d_in[4];
    const float* pp_b1   = (const float*)d_in[5];
    const float* pp_w2   = (const float*)d_in[6];
    const float* pp_b2   = (const float*)d_in[7];
    const float* msg_w1  = (const float*)d_in[8];
    const float* msg_b1  = (const float*)d_in[9];
    const float* msg_w2  = (const float*)d_in[10];
    const float* msg_b2  = (const float*)d_in[11];
    const float* ed_w    = (const float*)d_in[12];
    const float* ed_b    = (const float*)d_in[13];
    const float* em_w1   = (const float*)d_in[14];
    const float* em_b1   = (const float*)d_in[15];
    const float* em_w2   = (const float*)d_in[16];
    const float* em_b2   = (const float*)d_in[17];
    const float* em_w3   = (const float*)d_in[18];
    const float* em_b3   = (const float*)d_in[19];
    const float* alpha_w = (const float*)d_in[20];
    const float* alpha_b = (const float*)d_in[21];
    const float* bias_w  = (const float*)d_in[22];
    const float* bias_b  = (const float*)d_in[23];
    float* out = (float*)d_out;

    cudaFuncSetAttribute(k_t1,   cudaFuncAttributeMaxDynamicSharedMemorySize, T1_SMEM);
    cudaFuncSetAttribute(k_edge, cudaFuncAttributeMaxDynamicSharedMemorySize, EDGE_SMEM);
    cudaFuncSetAttribute(k_cam,  cudaFuncAttributeMaxDynamicSharedMemorySize, CAM_SMEM);

    k_pre<<<8193,256>>>(feats, logits, labels);
    k_protonorm<<<C,256>>>();
    { dim3 g(C,4); k_cos<<<g,256>>>(); }
    { dim3 g(10,16); k_t1<<<g,512,T1_SMEM>>>(pp_w1, pp_b1); }
    k_hz<<<10,512>>>(pp_w2, pp_b2, ed_w, ed_b);
    { dim3 g(C,2); k_edge<<<g,256,EDGE_SMEM>>>(em_w1, em_b1, em_w2, em_b2, em_w3, em_b3); }
    k_graph<<<1,256>>>(prior, out);
    k_gnn<<<10,512>>>(msg_w1, msg_b1, msg_w2, msg_b2);
    { dim3 g(10,8); k_aw1<<<g,512>>>(alpha_w, alpha_b); }
    k_aw2<<<C,256>>>(bias_w, bias_b, out);
    k_refined<<<1,256>>>(logits, labels, out);
    { dim3 g(HW/128, BATCH); k_cam<<<g,320,CAM_SMEM>>>(feats, out + OUT_AW); }
    k_minmax<<<BATCH*C,256>>>(out);

    (void)in_sizes; (void)n_in; (void)out_size;
}

// round 17
// speedup vs baseline: 1.1132x; 1.0858x over previous
#include <cuda_runtime.h>
#include <cuda_bf16.h>
#include <math.h>

// ---------------- constants ----------------
#define BATCH 32
#define C 80
#define F 2048
#define HW 1024
#define HID 256
#define EDD 64
#define EIN 259            // 4*EDD + 3
#define TEMP_INV 0.4f      // 1/2.5
#define BETA_POS 0.5f
#define GAMMA_NEG 0.25f

// output offsets (flat concat of tuple: W_adj, aw, dlog, cam_vis, refined, total)
#define OUT_WADJ 0
#define OUT_AW   (C*C)                       // 6400
#define OUT_DLOG (OUT_AW + C*F)              // 170240
#define OUT_CAM  (OUT_DLOG + C)              // 170320
#define OUT_REF  (OUT_CAM + BATCH*C*HW)      // 2791760
#define OUT_TOT  (OUT_REF + BATCH*C)         // 2794320

// ---------------- scratch ----------------
struct Scratch {
    float pooledT[F*BATCH];      // [f][b]
    float probs[BATCH*C];
    float yv[BATCH*C];
    float wsum[C];
    float freq[C];
    float Pb[BATCH];
    float present[C];
    float proto[C*F];
    float nrm[C];
    float cosm[C*C];
    float t1[C*HID];
    float Hn[C*HID];
    float Zd[C*EDD];
    float r[C*C];
    float Wadj[C*C];
    float Amat[C*C];
    float Z[C*HID];
    float awun[C*F];
    float dlog[C];
    float lossbuf[4];
    float cam[(size_t)BATCH*C*HW];
};
__device__ Scratch g_s;

__device__ __forceinline__ float sigm(float x){ return 1.f/(1.f+expf(-x)); }
__device__ __forceinline__ float softplusf(float x){ return fmaxf(x,0.f)+log1pf(expf(-fabsf(x))); }
__device__ __forceinline__ float bcef(float h,float t){ return fmaxf(h,0.f)-h*t+log1pf(expf(-fabsf(h))); }

__device__ __forceinline__ unsigned cvt_tf32(float f){
    unsigned r;
    asm("cvt.rna.tf32.f32 %0, %1;" : "=r"(r) : "f"(f));
    return r;
}

// ---------------- K1: pooled (transposed) + small stats ----------------
__global__ void k_pre(const float* __restrict__ feats, const float* __restrict__ logits,
                      const int* __restrict__ labels){
    if (blockIdx.x < 8192){
        int row = blockIdx.x*8 + (threadIdx.x>>5);
        int lane = threadIdx.x & 31;
        const float4* p = (const float4*)(feats + (size_t)row*HW);
        float s = 0.f;
        #pragma unroll
        for (int i=0;i<8;i++){ float4 v = p[lane + i*32]; s += (v.x+v.y)+(v.z+v.w); }
        #pragma unroll
        for (int o=16;o>0;o>>=1) s += __shfl_down_sync(0xffffffffu,s,o);
        if (lane==0){
            int b = row >> 11, f = row & 2047;
            g_s.pooledT[f*BATCH + b] = s * (1.f/HW);
        }
    } else {
        int t = threadIdx.x;
        for (int i=t;i<BATCH*C;i+=256){
            float p = sigm(logits[i]);
            g_s.probs[i]=p;
            g_s.yv[i]=fmaxf((float)labels[i],0.f);
        }
        __syncthreads();
        if (t<C){
            float s=0.f, pr=0.f;
            for (int b=0;b<BATCH;b++){ s+=g_s.probs[b*C+t]; pr=fmaxf(pr,g_s.yv[b*C+t]); }
            g_s.wsum[t]=fmaxf(s,1e-6f); g_s.freq[t]=s*(1.f/BATCH);
            g_s.present[t]= pr>0.f ? 1.f : 0.f;
        }
        if (t>=128 && t<128+BATCH){
            int b=t-128; float s=0.f;
            for (int c=0;c<C;c++) s+=g_s.probs[b*C+c];
            g_s.Pb[b]=s;
        }
    }
}

// ---------------- K2: proto row + norm, block per class ----------------
__global__ void k_protonorm(){
    int c = blockIdx.x, t = threadIdx.x;
    __shared__ float pc[BATCH];
    __shared__ float red[256];
    if (t < BATCH) pc[t] = g_s.probs[t*C + c];
    __syncthreads();
    float invw = 1.f/g_s.wsum[c];
    float ss = 0.f;
    #pragma unroll
    for (int i=0;i<8;i++){
        int f = i*256 + t;
        const float4* p = (const float4*)(g_s.pooledT + f*BATCH);
        float s = 0.f;
        #pragma unroll
        for (int q=0;q<8;q++){
            float4 v = p[q];
            s += pc[q*4]*v.x + pc[q*4+1]*v.y + pc[q*4+2]*v.z + pc[q*4+3]*v.w;
        }
        float pv = s*invw;
        g_s.proto[(size_t)c*F + f] = pv;
        ss += pv*pv;
    }
    red[t]=ss; __syncthreads();
    for (int o=128;o>0;o>>=1){ if(t<o) red[t]+=red[t+o]; __syncthreads(); }
    if (t==0) g_s.nrm[c] = fmaxf(sqrtf(red[0]),1e-6f);
}

// ---------------- K3: cos, grid (C,4): 20 j per block ----------------
__global__ void k_cos(){
    int i = blockIdx.x;
    __shared__ float si[F];
    for (int k=threadIdx.x;k<F;k+=256) si[k]=g_s.proto[(size_t)i*F+k];
    __syncthreads();
    int w = threadIdx.x>>5, lane = threadIdx.x&31;
    float ni = g_s.nrm[i];
    int jend = blockIdx.y*20 + 20;
    for (int j=blockIdx.y*20+w; j<jend; j+=8){
        const float* pj = g_s.proto + (size_t)j*F;
        float s=0.f;
        #pragma unroll 8
        for (int k=lane;k<F;k+=32) s += si[k]*pj[k];
        #pragma unroll
        for (int o=16;o>0;o>>=1) s += __shfl_down_sync(0xffffffffu,s,o);
        if (lane==0){
            float v = s/(ni*g_s.nrm[j]);
            g_s.cosm[i*C+j] = fminf(fmaxf(v,-1.f),1.f);
        }
    }
}

// ---------------- K4: t1 = relu(proto@pp_w1+b1), grid (10,16), 512 thr ----------------
#define T1_SMEM ((8*2048 + 32*8*16)*4)   // 64KB sx + 16KB red = 80KB
__global__ void k_t1(const float* __restrict__ W, const float* __restrict__ bias){
    extern __shared__ float sm4[];
    float* sx = sm4;            // [8][2048]
    float* red = sm4 + 8*2048;  // [32 kg][8 r][16 jl]
    int m0 = blockIdx.x*8;
    int bj = blockIdx.y;
    int t = threadIdx.x;
    {
        float4* d4 = (float4*)sx;
        const float4* s4 = (const float4*)(g_s.proto + (size_t)m0*F);
        #pragma unroll
        for (int l=t; l<(8*F)/4; l+=512) d4[l] = s4[l];
    }
    __syncthreads();
    int jl = t & 15, kg = t >> 4;   // kg 0..31
    const float* Wp = W + (size_t)(kg*64)*HID + bj*16 + jl;
    float acc[8];
    #pragma unroll
    for (int r=0;r<8;r++) acc[r]=0.f;
    #pragma unroll 16
    for (int k=0;k<64;k++){
        float w = Wp[(size_t)k*HID];
        int ka = kg*64 + k;
        #pragma unroll
        for (int r=0;r<8;r++) acc[r] += sx[r*F+ka]*w;
    }
    #pragma unroll
    for (int r=0;r<8;r++) red[kg*128 + r*16 + jl] = acc[r];
    __syncthreads();
    if (t < 128){
        int r = t>>4, jo = t&15;
        int j = bj*16 + jo;
        float s = 0.f;
        #pragma unroll
        for (int q=0;q<32;q++) s += red[q*128 + r*16 + jo];
        g_s.t1[(size_t)(m0+r)*HID + j] = fmaxf(s + bias[j], 0.f);
    }
}

// ---------------- K5: Hn = t1@pp_w2+b2 ; Zd = relu(Hn@ed_w+ed_b), grid 10, 512 thr ----------------
__global__ void k_hz(const float* __restrict__ W2, const float* __restrict__ b2,
                     const float* __restrict__ EW, const float* __restrict__ EB){
    __shared__ float sx[8*HID];
    __shared__ float sh[8*HID];
    __shared__ float part[8*512];
    int m0 = blockIdx.x*8, t = threadIdx.x;
    {
        float4* d4 = (float4*)sx;
        const float4* s4 = (const float4*)(g_s.t1 + (size_t)m0*HID);
        for (int l=t; l<(8*HID)/4; l+=512) d4[l] = s4[l];
    }
    __syncthreads();
    int j = t & 255, kg = t >> 8;
    float acc[8];
    #pragma unroll
    for (int r=0;r<8;r++) acc[r]=0.f;
    #pragma unroll 8
    for (int k=0;k<128;k++){
        int ka = kg*128 + k;
        float w = W2[(size_t)ka*HID + j];
        #pragma unroll
        for (int r=0;r<8;r++) acc[r] += sx[r*HID+ka]*w;
    }
    if (kg==1){
        #pragma unroll
        for (int r=0;r<8;r++) part[r*256+j] = acc[r];
    }
    __syncthreads();
    if (kg==0){
        float bv = b2[j];
        #pragma unroll
        for (int r=0;r<8;r++){
            float v = acc[r] + part[r*256+j] + bv;
            g_s.Hn[(size_t)(m0+r)*HID + j] = v;
            sh[r*HID+j] = v;
        }
    }
    __syncthreads();
    int j2 = t & 63, kg2 = t >> 6;
    float a2[8];
    #pragma unroll
    for (int r=0;r<8;r++) a2[r]=0.f;
    #pragma unroll 8
    for (int k=0;k<32;k++){
        int ka = kg2*32 + k;
        float w = EW[(size_t)ka*EDD + j2];
        #pragma unroll
        for (int r=0;r<8;r++) a2[r] += sh[r*HID+ka]*w;
    }
    #pragma unroll
    for (int r=0;r<8;r++) part[kg2*512 + r*64 + j2] = a2[r];
    __syncthreads();
    {
        int r3 = t >> 6, j3 = t & 63;
        float s = 0.f;
        #pragma unroll
        for (int q=0;q<8;q++) s += part[q*512 + r3*64 + j3];
        g_s.Zd[(size_t)(m0+r3)*EDD + j3] = fmaxf(s + EB[j3], 0.f);
    }
}

// ---------------- K6: edge MLP, grid (80,2), 5 steps x 8 edges ----------------
__global__ void k_edge(const float* __restrict__ w1, const float* __restrict__ b1,
                       const float* __restrict__ w2, const float* __restrict__ b2,
                       const float* __restrict__ w3, const float* __restrict__ b3){
    extern __shared__ float sm6[];
    float* sw1 = sm6;                // 259*128
    float* sw2 = sw1 + EIN*128;      // 128*64
    float* sw3 = sw2 + 128*64;       // 64
    float* sb1 = sw3 + 64;           // 128
    float* sb2 = sb1 + 128;          // 64
    float* szi = sb2 + 64;           // 64
    float* sfeat = szi + 64;         // 8 edges * 264
    float* sh1 = sfeat + 8*264;      // 8*128
    float* sh2 = sh1 + 8*128;        // 8*64
    int tid = threadIdx.x;
    #pragma unroll 8
    for (int i=tid;i<EIN*128;i+=256) sw1[i]=w1[i];
    #pragma unroll 8
    for (int i=tid;i<128*64;i+=256)  sw2[i]=w2[i];
    if (tid<64)  sw3[tid]=w3[tid];
    if (tid<128) sb1[tid]=b1[tid];
    if (tid<64)  sb2[tid]=b2[tid];
    int iRow = blockIdx.x;
    if (tid<64) szi[tid]=g_s.Zd[iRow*EDD+tid];
    float b3v = b3[0];
    float fi = g_s.freq[iRow];
    __syncthreads();
    int g = tid>>7, lt = tid&127;
    for (int step=0;step<5;step++){
        int jb = blockIdx.y*40 + step*8 + g*4;
        float* fg = sfeat + g*4*264;
        if (lt<64){
            float zi = szi[lt];
            #pragma unroll
            for (int e=0;e<4;e++){
                float zj = g_s.Zd[(jb+e)*EDD + lt];
                float* f = fg + e*264;
                f[lt]      = zi;
                f[64+lt]   = zj;
                f[128+lt]  = fabsf(zi-zj);
                f[192+lt]  = zi*zj;
            }
        } else if (lt==64){
            #pragma unroll
            for (int e=0;e<4;e++){
                float* f = fg + e*264;
                f[256] = g_s.cosm[iRow*C+jb+e];
                f[257] = fi;
                f[258] = g_s.freq[jb+e];
            }
        }
        __syncthreads();
        {
            float a[4] = {0.f,0.f,0.f,0.f};
            #pragma unroll 4
            for (int k=0;k<EIN;k++){
                float w = sw1[k*128+lt];
                #pragma unroll
                for (int e=0;e<4;e++) a[e] += fg[e*264+k]*w;
            }
            float bb = sb1[lt];
            #pragma unroll
            for (int e=0;e<4;e++) sh1[(g*4+e)*128+lt] = fmaxf(a[e]+bb,0.f);
        }
        __syncthreads();
        if (lt<64){
            float a[4] = {0.f,0.f,0.f,0.f};
            #pragma unroll 4
            for (int k=0;k<128;k++){
                float w = sw2[k*64+lt];
                #pragma unroll
                for (int e=0;e<4;e++) a[e] += sh1[(g*4+e)*128+k]*w;
            }
            float bb = sb2[lt];
            #pragma unroll
            for (int e=0;e<4;e++) sh2[(g*4+e)*64+lt] = fmaxf(a[e]+bb,0.f);
        }
        __syncthreads();
        if (lt<32){
            #pragma unroll
            for (int e=0;e<4;e++){
                float v = sh2[(g*4+e)*64+lt]*sw3[lt] + sh2[(g*4+e)*64+32+lt]*sw3[32+lt];
                #pragma unroll
                for (int o=16;o>0;o>>=1) v += __shfl_down_sync(0xffffffffu,v,o);
                if (lt==0) g_s.r[iRow*C+jb+e] = v + b3v;
            }
        }
        __syncthreads();
    }
}
#define EDGE_SMEM ((EIN*128 + 128*64 + 64 + 128 + 64 + 64 + 8*264 + 8*128 + 8*64)*4)

// ---------------- K7: W_adj, A, edge losses, sparsity (1 block) ----------------
__global__ void k_graph(const float* __restrict__ prior, float* __restrict__ out){
    __shared__ float sW[C*C];
    __shared__ float rs[C];
    __shared__ float red[256];
    __shared__ float params[2];
    int t = threadIdx.x;
    for (int idx=t; idx<C*C; idx+=256){
        int i=idx/C, j=idx%C;
        float hij = prior[idx]*TEMP_INV + g_s.r[idx];
        float hji = prior[j*C+i]*TEMP_INV + g_s.r[j*C+i];
        float w = 0.5f*(sigm(hij)+sigm(hji));
        if (i==j) w=0.f;
        sW[idx]=w; g_s.Wadj[idx]=w; out[OUT_WADJ+idx]=w;
    }
    __syncthreads();
    if (t<C){ float s=0.f; for (int j=0;j<C;j++) s+=sW[t*C+j]; rs[t]=fmaxf(s,1e-6f); }
    __syncthreads();
    for (int idx=t; idx<C*C; idx+=256) g_s.Amat[idx]=sW[idx]/rs[idx/C];
    float aP=0.f,aN=0.f,aE=0.f;
    for (int idx=t; idx<C*C; idx+=256){
        int i=idx/C, j=idx%C;
        float em = (i!=j && g_s.present[i]>0.f && g_s.present[j]>0.f)?1.f:0.f;
        float tv = sigm(prior[idx]*TEMP_INV);
        float pf = tv>0.5f?1.f:0.f;
        aP+=pf*em; aN+=(1.f-pf)*em; aE+=em;
    }
    red[t]=aP; __syncthreads();
    for (int o=128;o>0;o>>=1){ if(t<o) red[t]+=red[t+o]; __syncthreads(); }
    float nP = fmaxf(red[0],1.f); __syncthreads();
    red[t]=aN; __syncthreads();
    for (int o=128;o>0;o>>=1){ if(t<o) red[t]+=red[t+o]; __syncthreads(); }
    float nN = fmaxf(red[0],1.f); __syncthreads();
    red[t]=aE; __syncthreads();
    for (int o=128;o>0;o>>=1){ if(t<o) red[t]+=red[t+o]; __syncthreads(); }
    if (t==0){
        params[0] = fminf(fmaxf(nN/nP,1.f),10.f);
        params[1] = fmaxf(red[0],1.f);
    }
    __syncthreads();
    float wpos = params[0], nedges = params[1];
    float aL=0.f,aR=0.f,aS=0.f;
    for (int idx=t; idx<C*C; idx+=256){
        int i=idx/C, j=idx%C;
        float em = (i!=j && g_s.present[i]>0.f && g_s.present[j]>0.f)?1.f:0.f;
        float tv = sigm(prior[idx]*TEMP_INV);
        float h  = prior[idx]*TEMP_INV + g_s.r[idx];
        float wgt = (tv>0.5f)? wpos : 1.f;
        aL += bcef(h,tv)*wgt*em;
        aR += fabsf(g_s.r[idx])*em;
        aS += sW[idx];
    }
    red[t]=aL; __syncthreads();
    for (int o=128;o>0;o>>=1){ if(t<o) red[t]+=red[t+o]; __syncthreads(); }
    float SL = red[0]; __syncthreads();
    red[t]=aR; __syncthreads();
    for (int o=128;o>0;o>>=1){ if(t<o) red[t]+=red[t+o]; __syncthreads(); }
    float SR = red[0]; __syncthreads();
    red[t]=aS; __syncthreads();
    for (int o=128;o>0;o>>=1){ if(t<o) red[t]+=red[t+o]; __syncthreads(); }
    if (t==0){
        g_s.lossbuf[0]=SL/nedges;
        g_s.lossbuf[1]=0.001f*SR/nedges;
        g_s.lossbuf[2]=red[0]/(float)(C*C);
    }
}

// ---------------- K8: GNN step, grid 10, 512 thr ----------------
__global__ void k_gnn(const float* __restrict__ mw1, const float* __restrict__ mb1,
                      const float* __restrict__ mw2, const float* __restrict__ mb2){
    __shared__ float sA[8*C];
    __shared__ float s1[8*HID];
    __shared__ float s2[8*HID];
    __shared__ float part[8*256];
    int m0 = blockIdx.x*8, t = threadIdx.x;
    for (int l=t;l<8*C;l+=512) sA[l]=g_s.Amat[m0*C + l];
    __syncthreads();
    int j = t & 255, kg = t >> 8;
    float acc[8];
    #pragma unroll
    for (int r=0;r<8;r++) acc[r]=0.f;
    #pragma unroll 8
    for (int k=0;k<40;k++){
        int c = kg*40 + k;
        float h = g_s.Hn[(size_t)c*HID + j];
        #pragma unroll
        for (int r=0;r<8;r++) acc[r]+=sA[r*C+c]*h;
    }
    if (kg==1){
        #pragma unroll
        for (int r=0;r<8;r++) part[r*256+j]=acc[r];
    }
    __syncthreads();
    if (kg==0){
        #pragma unroll
        for (int r=0;r<8;r++) s1[r*HID+j] = acc[r] + part[r*256+j];
    }
    __syncthreads();
    float m[8];
    #pragma unroll
    for (int r=0;r<8;r++) m[r]=0.f;
    #pragma unroll 8
    for (int k=0;k<128;k++){
        int ka = kg*128 + k;
        float w = mw1[(size_t)ka*HID+j];
        #pragma unroll
        for (int r=0;r<8;r++) m[r]+=s1[r*HID+ka]*w;
    }
    if (kg==1){
        #pragma unroll
        for (int r=0;r<8;r++) part[r*256+j]=m[r];
    }
    __syncthreads();
    if (kg==0){
        float mb = mb1[j];
        #pragma unroll
        for (int r=0;r<8;r++) s2[r*HID+j] = fmaxf(m[r]+part[r*256+j]+mb, 0.f);
    }
    __syncthreads();
    float z[8];
    #pragma unroll
    for (int r=0;r<8;r++) z[r]=0.f;
    #pragma unroll 8
    for (int k=0;k<128;k++){
        int ka = kg*128 + k;
        float w = mw2[(size_t)ka*HID+j];
        #pragma unroll
        for (int r=0;r<8;r++) z[r]+=s2[r*HID+ka]*w;
    }
    if (kg==1){
        #pragma unroll
        for (int r=0;r<8;r++) part[r*256+j]=z[r];
    }
    __syncthreads();
    if (kg==0){
        float b2 = mb2[j];
        #pragma unroll
        for (int r=0;r<8;r++)
            g_s.Z[(size_t)(m0+r)*HID+j] =
                fmaxf(g_s.Hn[(size_t)(m0+r)*HID+j] + z[r] + part[r*256+j] + b2, 0.f);
    }
}

// ---------------- K9: aw unnormalized, grid (10,8), 512 thr ----------------
__global__ void k_aw1(const float* __restrict__ AW, const float* __restrict__ AB){
    __shared__ float z[8*HID];
    __shared__ float part[8*256];
    int c0 = blockIdx.x*8, bj = blockIdx.y, t = threadIdx.x;
    {
        float4* d4 = (float4*)z;
        const float4* s4 = (const float4*)(g_s.Z + (size_t)c0*HID);
        for (int l=t; l<(8*HID)/4; l+=512) d4[l] = s4[l];
    }
    __syncthreads();
    int j = t & 255, kg = t >> 8;
    int jg = bj*256 + j;
    float acc[8];
    #pragma unroll
    for (int r=0;r<8;r++) acc[r]=0.f;
    #pragma unroll 16
    for (int k=0;k<128;k++){
        int ka = kg*128 + k;
        float w = AW[(size_t)ka*F + jg];
        #pragma unroll
        for (int r=0;r<8;r++) acc[r]+=z[r*HID+ka]*w;
    }
    if (kg==1){
        #pragma unroll
        for (int r=0;r<8;r++) part[r*256+j]=acc[r];
    }
    __syncthreads();
    if (kg==0){
        float b = AB[jg];
        #pragma unroll
        for (int r=0;r<8;r++)
            g_s.awun[(size_t)(c0+r)*F + jg] = softplusf(acc[r]+part[r*256+j]+b);
    }
}

// ---------------- K10: normalize aw, write out, compute dlog. grid 80 ----------------
__global__ void k_aw2(const float* __restrict__ bias_w, const float* __restrict__ bias_b,
                      float* __restrict__ out){
    __shared__ float red[256];
    int c = blockIdx.x, t = threadIdx.x;
    float vals[8]; float s=0.f;
    #pragma unroll
    for (int i=0;i<8;i++){ vals[i]=g_s.awun[(size_t)c*F + i*256 + t]; s+=vals[i]; }
    red[t]=s; __syncthreads();
    for (int o=128;o>0;o>>=1){ if(t<o) red[t]+=red[t+o]; __syncthreads(); }
    float inv = 1.f/fmaxf(red[0],1e-6f);
    #pragma unroll
    for (int i=0;i<8;i++) out[OUT_AW + (size_t)c*F + i*256 + t] = vals[i]*inv;
    __syncthreads();
    red[t] = g_s.Z[(size_t)c*HID + t]*bias_w[t]; __syncthreads();
    for (int o=128;o>0;o>>=1){ if(t<o) red[t]+=red[t+o]; __syncthreads(); }
    if (t==0){ float d = red[0]+bias_b[0]; g_s.dlog[c]=d; out[OUT_DLOG+c]=d; }
}

// ---------------- K11: refined + cls_loss + total (1 block) ----------------
__global__ void k_refined(const float* __restrict__ logits, const int* __restrict__ labels,
                          float* __restrict__ out){
    __shared__ float sW[C*C];
    __shared__ float sq[BATCH*C];
    __shared__ float red[256];
    int t = threadIdx.x;
    for (int i=t;i<C*C;i+=256) sW[i]=g_s.Wadj[i];
    for (int i=t;i<BATCH*C;i+=256) sq[i]=g_s.probs[i]*g_s.yv[i];
    __syncthreads();
    float accL=0.f, accM=0.f;
    for (int idx=t; idx<BATCH*C; idx+=256){
        int b=idx/C, d=idx%C;
        float s=0.f;
        #pragma unroll 4
        for (int c=0;c<C;c++) s += sq[b*C+c]*sW[c*C+d];
        float pos = g_s.yv[idx]*s;
        float neg = g_s.Pb[b] - pos;
        float ref = logits[idx] + BETA_POS*pos - GAMMA_NEG*neg + g_s.dlog[d];
        out[OUT_REF+idx] = ref;
        float lab = (float)labels[idx];
        float mflag = (lab != -1.f) ? 1.f : 0.f;
        float safe_t = (mflag>0.f)? lab : 0.f;
        accL += bcef(ref,safe_t)*mflag;
        accM += mflag;
    }
    red[t]=accL; __syncthreads();
    for (int o=128;o>0;o>>=1){ if(t<o) red[t]+=red[t+o]; __syncthreads(); }
    float SL=red[0]; __syncthreads();
    red[t]=accM; __syncthreads();
    for (int o=128;o>0;o>>=1){ if(t<o) red[t]+=red[t+o]; __syncthreads(); }
    if (t==0){
        float cls = SL/fmaxf(red[0],1.f);
        out[OUT_TOT] = cls + 0.1f*g_s.lossbuf[0] + g_s.lossbuf[1] + 0.01f*g_s.lossbuf[2];
    }
}

// ---------------- K12: cam GEMM via tf32 mma.sync, single-pass, 3-stage pipeline ----------------
#define BS_STRIDE 136
#define AS_STRIDE 36
#define CAM_SMEM ((3*32*BS_STRIDE + 80*AS_STRIDE)*4)   // 52224 + 11520 = 63744 B

__device__ __forceinline__ void mma_tf32(float* c, const unsigned* a, unsigned b0, unsigned b1){
    asm volatile(
        "mma.sync.aligned.m16n8k8.row.col.f32.tf32.tf32.f32 "
        "{%0,%1,%2,%3}, {%4,%5,%6,%7}, {%8,%9}, {%0,%1,%2,%3};\n"
        : "+f"(c[0]), "+f"(c[1]), "+f"(c[2]), "+f"(c[3])
        : "r"(a[0]), "r"(a[1]), "r"(a[2]), "r"(a[3]), "r"(b0), "r"(b1));
}

__global__ void __launch_bounds__(320,2) k_cam(const float* __restrict__ feats,
                                               const float* __restrict__ aw){
    extern __shared__ float smem[];
    float* sB = smem;                                  // [3][32][136]
    unsigned* sA = (unsigned*)(smem + 3*32*BS_STRIDE); // [80][36]
    int tid = threadIdx.x;
    int lane = tid & 31;
    int w = tid >> 5;
    int g = lane >> 2, tg = lane & 3;
    int wm = w % 5, wn = w / 5;
    int m0 = wm*16;
    int ncol0 = wn*64;
    int nbase = blockIdx.x * 128;
    int b = blockIdx.y;
    const float* Bp = feats + (size_t)b*F*HW + nbase;

    float acc[8][4];
    #pragma unroll
    for (int s=0;s<8;s++)
        #pragma unroll
        for (int i=0;i<4;i++) acc[s][i]=0.f;

    // prologue: issue tiles 0 and 1
    #pragma unroll
    for (int pk=0; pk<2; pk++){
        unsigned base = (unsigned)__cvta_generic_to_shared(sB + (pk%3)*32*BS_STRIDE);
        const float* Bn = Bp + (size_t)pk*32*HW;
        for (int l=tid; l<1024; l+=320){
            int kk = l>>5, c4 = l&31;
            unsigned dst = base + (kk*BS_STRIDE + c4*4)*4;
            const float* src = Bn + (size_t)kk*HW + c4*4;
            asm volatile("cp.async.cg.shared.global [%0], [%1], 16;" :: "r"(dst), "l"(src));
        }
        asm volatile("cp.async.commit_group;");
    }

    for (int kt=0; kt<64; kt++){
        int buf = kt % 3;
        __syncthreads();   // prev MMA done: sA free, sB[(kt+2)%3] free
        // A fill: single tf32 cvt (aw L2-resident)
        {
            int l = tid;
            #pragma unroll
            for (int it=0; it<2; it++, l+=320){
                int m = l>>3, k4 = l&7;
                float4 v = *(const float4*)(aw + (size_t)m*F + kt*32 + k4*4);
                unsigned* hi = sA + m*AS_STRIDE + k4*4;
                hi[0]=cvt_tf32(v.x); hi[1]=cvt_tf32(v.y);
                hi[2]=cvt_tf32(v.z); hi[3]=cvt_tf32(v.w);
            }
        }
        // issue tile kt+2; wait for tile kt's group
        if (kt+2 < 64){
            unsigned base = (unsigned)__cvta_generic_to_shared(sB + ((kt+2)%3)*32*BS_STRIDE);
            const float* Bn = Bp + (size_t)(kt+2)*32*HW;
            for (int l=tid; l<1024; l+=320){
                int kk = l>>5, c4 = l&31;
                unsigned dst = base + (kk*BS_STRIDE + c4*4)*4;
                const float* src = Bn + (size_t)kk*HW + c4*4;
                asm volatile("cp.async.cg.shared.global [%0], [%1], 16;" :: "r"(dst), "l"(src));
            }
            asm volatile("cp.async.commit_group;");
            asm volatile("cp.async.wait_group 2;");
        } else if (kt+1 < 64){
            asm volatile("cp.async.wait_group 1;");
        } else {
            asm volatile("cp.async.wait_group 0;");
        }
        // self-cvt: each thread converts exactly the chunks IT cp.async'd
        {
            float* Bb = sB + buf*32*BS_STRIDE;
            for (int l=tid; l<1024; l+=320){
                int kk = l>>5, c4 = l&31;
                float4 v = *(float4*)(Bb + kk*BS_STRIDE + c4*4);
                uint4 u;
                u.x=cvt_tf32(v.x); u.y=cvt_tf32(v.y); u.z=cvt_tf32(v.z); u.w=cvt_tf32(v.w);
                *(uint4*)(Bb + kk*BS_STRIDE + c4*4) = u;
            }
        }
        __syncthreads();   // A fill + B cvt visible to all

        const unsigned* Bt = (const unsigned*)(sB + buf*32*BS_STRIDE);
        #pragma unroll
        for (int k8=0; k8<4; k8++){
            unsigned ahi[4];
            int arow0 = (m0+g)*AS_STRIDE + k8*8 + tg;
            int arow1 = (m0+8+g)*AS_STRIDE + k8*8 + tg;
            ahi[0]=sA[arow0];   ahi[1]=sA[arow1];
            ahi[2]=sA[arow0+4]; ahi[3]=sA[arow1+4];
            const unsigned* br0 = Bt + (k8*8+tg)*BS_STRIDE + ncol0 + g;
            const unsigned* br1 = br0 + 4*BS_STRIDE;
            #pragma unroll
            for (int s=0;s<8;s++){
                mma_tf32(acc[s], ahi, br0[s*8], br1[s*8]);
            }
        }
    }

    #pragma unroll
    for (int s=0;s<8;s++){
        int cb = nbase + ncol0 + s*8 + tg*2;
        float* d0 = g_s.cam + ((size_t)b*C + m0+g)*HW + cb;
        float* d1 = g_s.cam + ((size_t)b*C + m0+8+g)*HW + cb;
        d0[0]=acc[s][0]; d0[1]=acc[s][1];
        d1[0]=acc[s][2]; d1[1]=acc[s][3];
    }
}

// ---------------- K13: relu + min/max normalize ----------------
__global__ void k_minmax(float* __restrict__ out){
    __shared__ float rmn[256], rmx[256];
    int row = blockIdx.x, t = threadIdx.x;
    const float* base = g_s.cam + (size_t)row*HW;
    float v[4]; float mn=3.4e38f, mx=-3.4e38f;
    #pragma unroll
    for (int i=0;i<4;i++){
        v[i]=fmaxf(base[t+i*256],0.f);
        mn=fminf(mn,v[i]); mx=fmaxf(mx,v[i]);
    }
    rmn[t]=mn; rmx[t]=mx; __syncthreads();
    for (int o=128;o>0;o>>=1){
        if (t<o){ rmn[t]=fminf(rmn[t],rmn[t+o]); rmx[t]=fmaxf(rmx[t],rmx[t+o]); }
        __syncthreads();
    }
    mn=rmn[0]; mx=rmx[0];
    float inv = 1.f/(mx-mn+1e-6f);
    #pragma unroll
    for (int i=0;i<4;i++)
        out[OUT_CAM + (size_t)row*HW + t + i*256] = (v[i]-mn)*inv;
}

// ---------------- launch ----------------
extern "C" void kernel_launch(void* const* d_in, const int* in_sizes, int n_in,
                              void* d_out, int out_size){
    const float* feats   = (const float*)d_in[0];
    const float* logits  = (const float*)d_in[1];
    const int*   labels  = (const int*)d_in[2];
    const float* prior   = (const float*)d_in[3];
    const float* pp_w1   = (const float*)d_in[4];
    const float* pp_b1   = (const float*)d_in[5];
    const float* pp_w2   = (const float*)d_in[6];
    const float* pp_b2   = (const float*)d_in[7];
    const float* msg_w1  = (const float*)d_in[8];
    const float* msg_b1  = (const float*)d_in[9];
    const float* msg_w2  = (const float*)d_in[10];
    const float* msg_b2  = (const float*)d_in[11];
    const float* ed_w    = (const float*)d_in[12];
    const float* ed_b    = (const float*)d_in[13];
    const float* em_w1   = (const float*)d_in[14];
    const float* em_b1   = (const float*)d_in[15];
    const float* em_w2   = (const float*)d_in[16];
    const float* em_b2   = (const float*)d_in[17];
    const float* em_w3   = (const float*)d_in[18];
    const float* em_b3   = (const float*)d_in[19];
    const float* alpha_w = (const float*)d_in[20];
    const float* alpha_b = (const float*)d_in[21];
    const float* bias_w  = (const float*)d_in[22];
    const float* bias_b  = (const float*)d_in[23];
    float* out = (float*)d_out;

    cudaFuncSetAttribute(k_t1,   cudaFuncAttributeMaxDynamicSharedMemorySize, T1_SMEM);
    cudaFuncSetAttribute(k_edge, cudaFuncAttributeMaxDynamicSharedMemorySize, EDGE_SMEM);
    cudaFuncSetAttribute(k_cam,  cudaFuncAttributeMaxDynamicSharedMemorySize, CAM_SMEM);

    k_pre<<<8193,256>>>(feats, logits, labels);
    k_protonorm<<<C,256>>>();
    { dim3 g(C,4); k_cos<<<g,256>>>(); }
    { dim3 g(10,16); k_t1<<<g,512,T1_SMEM>>>(pp_w1, pp_b1); }
    k_hz<<<10,512>>>(pp_w2, pp_b2, ed_w, ed_b);
    { dim3 g(C,2); k_edge<<<g,256,EDGE_SMEM>>>(em_w1, em_b1, em_w2, em_b2, em_w3, em_b3); }
    k_graph<<<1,256>>>(prior, out);
    k_gnn<<<10,512>>>(msg_w1, msg_b1, msg_w2, msg_b2);
    { dim3 g(10,8); k_aw1<<<g,512>>>(alpha_w, alpha_b); }
    k_aw2<<<C,256>>>(bias_w, bias_b, out);
    k_refined<<<1,256>>>(logits, labels, out);
    { dim3 g(HW/128, BATCH); k_cam<<<g,320,CAM_SMEM>>>(feats, out + OUT_AW); }
    k_minmax<<<BATCH*C,256>>>(out);

    (void)in_sizes; (void)n_in; (void)out_size;
}